// round 1
// baseline (speedup 1.0000x reference)
#include <cuda_runtime.h>
#include <math.h>

#define D_MODEL 1024
#define N_HEADS 16
#define HEAD_DIM 64

// Scratch (allocation-free rule: __device__ globals)
__device__ float g_qkv[4096 * 3 * 1024];   // [T*B, 3D]
__device__ float g_ctx[4096 * 1024];       // [T*B, D]

// ---------------------------------------------------------------------------
// SGEMM: C[M,N] = A[M,K] @ B[K,N] + bias[N]
// 128x128 block tile, BK=8, 256 threads, 8x8 per-thread tile (2x2 float4)
// Requires M%128==0, N%128==0, K%8==0 (true here: M=4096, N in {3072,1024}, K=1024)
// ---------------------------------------------------------------------------
__global__ __launch_bounds__(256) void sgemm128(
    const float* __restrict__ A, const float* __restrict__ B,
    const float* __restrict__ bias, float* __restrict__ C,
    int M, int N, int K)
{
    __shared__ float As[8][128];   // transposed A tile
    __shared__ float Bs[8][128];

    const int tid = threadIdx.x;
    const int tx = tid & 15;        // 0..15 -> col groups
    const int ty = tid >> 4;        // 0..15 -> row groups
    const int bm = blockIdx.y * 128;
    const int bn = blockIdx.x * 128;

    const int aRow = tid >> 1;          // 0..127
    const int aCol = (tid & 1) * 4;     // 0 or 4
    const int bRow = tid >> 5;          // 0..7
    const int bCol = (tid & 31) * 4;    // 0..124

    const float* Aptr = A + (size_t)(bm + aRow) * K + aCol;
    const float* Bptr = B + (size_t)bRow * N + bn + bCol;

    float acc[8][8];
#pragma unroll
    for (int i = 0; i < 8; i++)
#pragma unroll
        for (int j = 0; j < 8; j++) acc[i][j] = 0.f;

    for (int k0 = 0; k0 < K; k0 += 8) {
        float4 a4 = *(const float4*)(Aptr + k0);
        float4 b4 = *(const float4*)(Bptr + (size_t)k0 * N);
        As[aCol + 0][aRow] = a4.x;
        As[aCol + 1][aRow] = a4.y;
        As[aCol + 2][aRow] = a4.z;
        As[aCol + 3][aRow] = a4.w;
        *(float4*)&Bs[bRow][bCol] = b4;
        __syncthreads();

#pragma unroll
        for (int kk = 0; kk < 8; kk++) {
            float a[8], b[8];
            *(float4*)(a)     = *(const float4*)&As[kk][ty * 4];
            *(float4*)(a + 4) = *(const float4*)&As[kk][ty * 4 + 64];
            *(float4*)(b)     = *(const float4*)&Bs[kk][tx * 4];
            *(float4*)(b + 4) = *(const float4*)&Bs[kk][tx * 4 + 64];
#pragma unroll
            for (int i = 0; i < 8; i++)
#pragma unroll
                for (int j = 0; j < 8; j++)
                    acc[i][j] += a[i] * b[j];
        }
        __syncthreads();
    }

    float bb[8];
#pragma unroll
    for (int j = 0; j < 8; j++)
        bb[j] = bias[bn + tx * 4 + (j & 3) + ((j >> 2) << 6)];

#pragma unroll
    for (int i = 0; i < 8; i++) {
        int row = bm + ty * 4 + (i & 3) + ((i >> 2) << 6);
        float* Crow = C + (size_t)row * N + bn + tx * 4;
        float4 o;
        o.x = acc[i][0] + bb[0]; o.y = acc[i][1] + bb[1];
        o.z = acc[i][2] + bb[2]; o.w = acc[i][3] + bb[3];
        *(float4*)(Crow) = o;
        o.x = acc[i][4] + bb[4]; o.y = acc[i][5] + bb[5];
        o.z = acc[i][6] + bb[6]; o.w = acc[i][7] + bb[7];
        *(float4*)(Crow + 64) = o;
    }
}

// ---------------------------------------------------------------------------
// Causal flash attention, fp32.
// Block: 256 threads = 8 warps; handles 64 queries of one (b,h).
// Each warp owns 8 query rows; each lane owns key columns {lane, lane+32}
// for scores and dims {lane, lane+32} for the context accumulator.
// smem: Q[64][64], K[64][68] (padded), V[64][64], P[8 warps][8][64]
// ---------------------------------------------------------------------------
#define QT 64
#define KT 64
#define RPW 8
#define KSTRIDE 68

__device__ __forceinline__ float warp_max(float v) {
#pragma unroll
    for (int off = 16; off; off >>= 1)
        v = fmaxf(v, __shfl_xor_sync(0xFFFFFFFFu, v, off));
    return v;
}
__device__ __forceinline__ float warp_sum(float v) {
#pragma unroll
    for (int off = 16; off; off >>= 1)
        v += __shfl_xor_sync(0xFFFFFFFFu, v, off);
    return v;
}

__global__ __launch_bounds__(256) void flash_fp32(
    const float* __restrict__ qkv, float* __restrict__ ctx, int T, int B)
{
    extern __shared__ float sm[];
    float* Qs = sm;                      // 64*64   = 4096
    float* Ks = Qs + QT * 64;            // 64*68   = 4352
    float* Vs = Ks + KT * KSTRIDE;       // 64*64   = 4096
    float* Ps = Vs + KT * 64;            // 8*8*64  = 4096

    const int qt = blockIdx.x;
    const int bh = blockIdx.y;          // b*N_HEADS + h
    const int b  = bh >> 4;
    const int h  = bh & 15;

    const int tid  = threadIdx.x;
    const int w    = tid >> 5;
    const int lane = tid & 31;
    const int t0   = qt * QT;

    const size_t rowstride = (size_t)B * 3 * D_MODEL;   // per-token row stride
    const float* qbase = qkv + ((size_t)t0 * B + b) * (3 * D_MODEL) + h * HEAD_DIM;
    const float* kbase = qkv + (size_t)b * (3 * D_MODEL) + D_MODEL + h * HEAD_DIM;
    const float* vbase = kbase + D_MODEL;

    // Load Q tile (scaled by 1/sqrt(Dh) = 0.125)
    for (int i = tid; i < QT * 16; i += 256) {
        int r = i >> 4, d4 = (i & 15) * 4;
        float4 v = *(const float4*)(qbase + (size_t)r * rowstride + d4);
        v.x *= 0.125f; v.y *= 0.125f; v.z *= 0.125f; v.w *= 0.125f;
        *(float4*)(&Qs[r * 64 + d4]) = v;
    }

    float m[RPW], l[RPW], acc0[RPW], acc1[RPW];
#pragma unroll
    for (int r = 0; r < RPW; r++) {
        m[r] = -1e30f; l[r] = 0.f; acc0[r] = 0.f; acc1[r] = 0.f;
    }

    for (int kt = 0; kt <= qt; kt++) {
        __syncthreads();   // also covers initial Q-load visibility
        const int kt0 = kt * KT;
        for (int i = tid; i < KT * 16; i += 256) {
            int r = i >> 4, d4 = (i & 15) * 4;
            size_t g = ((size_t)(kt0 + r) * B) * rowstride / ((size_t)B) ; // placeholder
            (void)g;
            const float* kp = kbase + ((size_t)(kt0 + r)) * rowstride + d4;
            const float* vp = vbase + ((size_t)(kt0 + r)) * rowstride + d4;
            *(float4*)(&Ks[r * KSTRIDE + d4]) = *(const float4*)kp;
            *(float4*)(&Vs[r * 64 + d4])      = *(const float4*)vp;
        }
        __syncthreads();

        const bool diag = (kt == qt);
        float* pw = &Ps[w * (RPW * 64)];

#pragma unroll
        for (int r = 0; r < RPW; r++) {
            const int row = w * RPW + r;
            const float* qrow = &Qs[row * 64];
            const float* k0p = &Ks[lane * KSTRIDE];
            const float* k1p = &Ks[(lane + 32) * KSTRIDE];
            float s0 = 0.f, s1 = 0.f;
#pragma unroll
            for (int d4 = 0; d4 < 16; d4++) {
                float4 q  = *(const float4*)(qrow + d4 * 4);
                float4 ka = *(const float4*)(k0p + d4 * 4);
                float4 kb = *(const float4*)(k1p + d4 * 4);
                s0 += q.x * ka.x + q.y * ka.y + q.z * ka.z + q.w * ka.w;
                s1 += q.x * kb.x + q.y * kb.y + q.z * kb.z + q.w * kb.w;
            }
            if (diag) {
                if (lane > row)      s0 = -1e30f;
                if (lane + 32 > row) s1 = -1e30f;
            }
            float tm = warp_max(fmaxf(s0, s1));
            float mnew = fmaxf(m[r], tm);
            float p0 = __expf(s0 - mnew);
            float p1 = __expf(s1 - mnew);
            float rs = warp_sum(p0 + p1);
            float alpha = __expf(m[r] - mnew);
            l[r] = l[r] * alpha + rs;
            acc0[r] *= alpha;
            acc1[r] *= alpha;
            m[r] = mnew;
            pw[r * 64 + lane]      = p0;
            pw[r * 64 + lane + 32] = p1;
        }
        __syncwarp();

#pragma unroll 4
        for (int k = 0; k < KT; k++) {
            float v0 = Vs[k * 64 + lane];
            float v1 = Vs[k * 64 + lane + 32];
#pragma unroll
            for (int r = 0; r < RPW; r++) {
                float p = pw[r * 64 + k];
                acc0[r] += p * v0;
                acc1[r] += p * v1;
            }
        }
        __syncwarp();
    }

    // Epilogue: ctx[t, b, h*64 + d]
#pragma unroll
    for (int r = 0; r < RPW; r++) {
        const int row = w * RPW + r;
        const float inv = 1.f / l[r];
        size_t o = ((size_t)(t0 + row) * B + b) * D_MODEL + h * HEAD_DIM;
        ctx[o + lane]      = acc0[r] * inv;
        ctx[o + lane + 32] = acc1[r] * inv;
    }
}

// ---------------------------------------------------------------------------
extern "C" void kernel_launch(void* const* d_in, const int* in_sizes, int n_in,
                              void* d_out, int out_size)
{
    const float* x    = (const float*)d_in[0];
    const float* Wqkv = (const float*)d_in[1];
    const float* bqkv = (const float*)d_in[2];
    const float* Wout = (const float*)d_in[3];
    const float* bout = (const float*)d_in[4];
    float* out = (float*)d_out;

    const int B = 2;
    const int M = in_sizes[0] / D_MODEL;   // T*B = 4096
    const int T = M / B;                   // 2048

    float *qkv, *ctx;
    cudaGetSymbolAddress((void**)&qkv, g_qkv);
    cudaGetSymbolAddress((void**)&ctx, g_ctx);

    // 1) QKV projection
    sgemm128<<<dim3((3 * D_MODEL) / 128, M / 128), 256>>>(
        x, Wqkv, bqkv, qkv, M, 3 * D_MODEL, D_MODEL);

    // 2) Causal flash attention
    const size_t smem = (QT * 64 + KT * KSTRIDE + KT * 64 + 8 * RPW * 64) * sizeof(float);
    cudaFuncSetAttribute(flash_fp32, cudaFuncAttributeMaxDynamicSharedMemorySize, (int)smem);
    flash_fp32<<<dim3(T / QT, B * N_HEADS), 256, smem>>>(qkv, ctx, T, B);

    // 3) Output projection
    sgemm128<<<dim3(D_MODEL / 128, M / 128), 256>>>(
        ctx, Wout, bout, out, M, D_MODEL, D_MODEL);
}

// round 3
// speedup vs baseline: 1.2620x; 1.2620x over previous
#include <cuda_runtime.h>
#include <cuda_bf16.h>
#include <cstdint>
#include <math.h>

#define D_MODEL 1024
#define N_HEADS 16
#define HEAD_DIM 64

// ---------------------------------------------------------------------------
// Scratch (allocation-free rule: __device__ globals)
// ---------------------------------------------------------------------------
__device__ float g_qkv[4096 * 3 * 1024];            // [T*B, 3D] fp32
__device__ float g_ctx[4096 * 1024];                // [T*B, D]  fp32
__device__ __nv_bfloat16 g_xhi[4096 * 1024];        // x split
__device__ __nv_bfloat16 g_xlo[4096 * 1024];
__device__ __nv_bfloat16 g_w1hi[3072 * 1024];       // Wqkv^T split  [N,K]
__device__ __nv_bfloat16 g_w1lo[3072 * 1024];
__device__ __nv_bfloat16 g_w2hi[1024 * 1024];       // Wout^T split  [N,K]
__device__ __nv_bfloat16 g_w2lo[1024 * 1024];
__device__ __nv_bfloat16 g_chi[4096 * 1024];        // ctx split
__device__ __nv_bfloat16 g_clo[4096 * 1024];

// ---------------------------------------------------------------------------
// PTX helpers (plain sm_103-compatible: mma.sync / ldmatrix / cp.async)
// ---------------------------------------------------------------------------
__device__ __forceinline__ uint32_t smem_to_u32(const void* p) {
    uint32_t a;
    asm("{ .reg .u64 t; cvta.to.shared.u64 t, %1; cvt.u32.u64 %0, t; }" : "=r"(a) : "l"(p));
    return a;
}

__device__ __forceinline__ void cp_async16(uint32_t dst, const void* src) {
    asm volatile("cp.async.ca.shared.global [%0], [%1], 16;" :: "r"(dst), "l"(src) : "memory");
}
#define CP_COMMIT() asm volatile("cp.async.commit_group;" ::: "memory")
#define CP_WAIT(n)  asm volatile("cp.async.wait_group %0;" :: "n"(n) : "memory")

__device__ __forceinline__ void ldsm_x4(uint32_t& r0, uint32_t& r1, uint32_t& r2, uint32_t& r3,
                                        uint32_t addr) {
    asm volatile("ldmatrix.sync.aligned.m8n8.x4.shared.b16 {%0,%1,%2,%3}, [%4];"
                 : "=r"(r0), "=r"(r1), "=r"(r2), "=r"(r3) : "r"(addr));
}

__device__ __forceinline__ void mma_bf16(float c[4], const uint32_t a[4], const uint32_t b[2]) {
    asm volatile(
        "mma.sync.aligned.m16n8k16.row.col.f32.bf16.bf16.f32 "
        "{%0,%1,%2,%3}, {%4,%5,%6,%7}, {%8,%9}, {%0,%1,%2,%3};"
        : "+f"(c[0]), "+f"(c[1]), "+f"(c[2]), "+f"(c[3])
        : "r"(a[0]), "r"(a[1]), "r"(a[2]), "r"(a[3]), "r"(b[0]), "r"(b[1]));
}

// ---------------------------------------------------------------------------
// Split-precision conversion kernels
// ---------------------------------------------------------------------------
__global__ __launch_bounds__(256) void split_convert(
    const float* __restrict__ in, __nv_bfloat16* __restrict__ hi,
    __nv_bfloat16* __restrict__ lo, int n4)
{
    int i = blockIdx.x * blockDim.x + threadIdx.x;
    if (i >= n4) return;
    float4 v = ((const float4*)in)[i];
    __nv_bfloat16 h0 = __float2bfloat16(v.x);
    __nv_bfloat16 h1 = __float2bfloat16(v.y);
    __nv_bfloat16 h2 = __float2bfloat16(v.z);
    __nv_bfloat16 h3 = __float2bfloat16(v.w);
    __nv_bfloat16 l0 = __float2bfloat16(v.x - __bfloat162float(h0));
    __nv_bfloat16 l1 = __float2bfloat16(v.y - __bfloat162float(h1));
    __nv_bfloat16 l2 = __float2bfloat16(v.z - __bfloat162float(h2));
    __nv_bfloat16 l3 = __float2bfloat16(v.w - __bfloat162float(h3));
    ((__nv_bfloat162*)hi)[i * 2]     = __halves2bfloat162(h0, h1);
    ((__nv_bfloat162*)hi)[i * 2 + 1] = __halves2bfloat162(h2, h3);
    ((__nv_bfloat162*)lo)[i * 2]     = __halves2bfloat162(l0, l1);
    ((__nv_bfloat162*)lo)[i * 2 + 1] = __halves2bfloat162(l2, l3);
}

// W[K,N] fp32 -> Wt_hi/Wt_lo [N,K] bf16 (transpose + split). 32x32 tiles.
__global__ __launch_bounds__(256) void split_convert_T(
    const float* __restrict__ W, __nv_bfloat16* __restrict__ hi,
    __nv_bfloat16* __restrict__ lo, int K, int N)
{
    __shared__ float t[32][33];
    const int n0 = blockIdx.x * 32;
    const int k0 = blockIdx.y * 32;
#pragma unroll
    for (int i = 0; i < 4; i++) {
        int k = k0 + threadIdx.y + i * 8;
        t[threadIdx.y + i * 8][threadIdx.x] = W[(size_t)k * N + n0 + threadIdx.x];
    }
    __syncthreads();
#pragma unroll
    for (int i = 0; i < 4; i++) {
        int nn = n0 + threadIdx.y + i * 8;
        float v = t[threadIdx.x][threadIdx.y + i * 8];
        __nv_bfloat16 h = __float2bfloat16(v);
        float r = v - __bfloat162float(h);
        hi[(size_t)nn * K + k0 + threadIdx.x] = h;
        lo[(size_t)nn * K + k0 + threadIdx.x] = __float2bfloat16(r);
    }
}

// ---------------------------------------------------------------------------
// HMMA bf16-split GEMM: C[M,N] = A[M,K] @ Bt[N,K]^T + bias
// CTA tile 128x128x32, 8 warps (4 in M x 2 in N), warp tile 32x64.
// 3-MMA split emulation: C += Ahi*Bhi + Ahi*Blo + Alo*Bhi.
// cp.async 3-stage pipeline; smem rows padded to 80B (conflict-free ldmatrix).
// ---------------------------------------------------------------------------
#define BK 32
#define ASTRIDE 40                     // bf16 elems per smem row (32 + 8 pad)
#define TILE_BYTES (128 * ASTRIDE * 2) // 10240
#define T_AHI 0
#define T_ALO (1 * TILE_BYTES)
#define T_BHI (2 * TILE_BYTES)
#define T_BLO (3 * TILE_BYTES)
#define STAGE_BYTES (4 * TILE_BYTES)   // 40960
#define STAGES 3
#define GSMEM_TOTAL (STAGES * STAGE_BYTES)  // 122880

__global__ __launch_bounds__(256, 1) void gemm_mma(
    const __nv_bfloat16* __restrict__ Ahi, const __nv_bfloat16* __restrict__ Alo,
    const __nv_bfloat16* __restrict__ Bhi, const __nv_bfloat16* __restrict__ Blo,
    const float* __restrict__ bias, float* __restrict__ C,
    int M, int N, int K)
{
    extern __shared__ char smem[];
    const uint32_t smem_base = smem_to_u32(smem);
    const int tid  = threadIdx.x;
    const int wid  = tid >> 5;
    const int lane = tid & 31;
    const int bm = blockIdx.y * 128;
    const int bn = blockIdx.x * 128;
    const int wm = (wid & 3) * 32;   // warp M offset within CTA tile
    const int wn = (wid >> 2) * 64;  // warp N offset

    const __nv_bfloat16* srcs[4]  = {Ahi, Alo, Bhi, Blo};
    const int rows0[4]            = {bm, bm, bn, bn};

    // load one k-stage (all four 128x32 tiles) via cp.async
    auto load_stage = [&](int it) {
        const uint32_t sb = smem_base + (it % STAGES) * STAGE_BYTES;
        const int k0 = it * BK;
#pragma unroll
        for (int c = tid; c < 2048; c += 256) {
            int mat = c >> 9;             // 0..3
            int r   = (c >> 2) & 127;     // row
            int kc  = (c & 3) * 8;        // bf16 col within 32
            const __nv_bfloat16* src = srcs[mat] + (size_t)(rows0[mat] + r) * K + k0 + kc;
            uint32_t dst = sb + mat * TILE_BYTES + (r * ASTRIDE + kc) * 2;
            cp_async16(dst, src);
        }
    };

    const int NK = K / BK;

    load_stage(0); CP_COMMIT();
    load_stage(1); CP_COMMIT();

    float acc[2][8][4];
#pragma unroll
    for (int mt = 0; mt < 2; mt++)
#pragma unroll
        for (int nt = 0; nt < 8; nt++)
#pragma unroll
            for (int i = 0; i < 4; i++) acc[mt][nt][i] = 0.f;

    // ldmatrix address components (lane-dependent)
    const int lrow = lane & 15;
    const int lcol = (lane >> 4) * 8;

    for (int kt = 0; kt < NK; kt++) {
        CP_WAIT(STAGES - 2);
        __syncthreads();

        if (kt + STAGES - 1 < NK) load_stage(kt + STAGES - 1);
        CP_COMMIT();

        const uint32_t sb = smem_base + (kt % STAGES) * STAGE_BYTES;

#pragma unroll
        for (int ks = 0; ks < 2; ks++) {
            uint32_t ah[2][4], al[2][4];
#pragma unroll
            for (int mt = 0; mt < 2; mt++) {
                uint32_t off = ((wm + mt * 16 + lrow) * ASTRIDE + ks * 16 + lcol) * 2;
                ldsm_x4(ah[mt][0], ah[mt][1], ah[mt][2], ah[mt][3], sb + T_AHI + off);
                ldsm_x4(al[mt][0], al[mt][1], al[mt][2], al[mt][3], sb + T_ALO + off);
            }
            uint32_t bh[8][2], bl[8][2];
#pragma unroll
            for (int np = 0; np < 4; np++) {
                uint32_t off = ((wn + np * 16 + lrow) * ASTRIDE + ks * 16 + lcol) * 2;
                uint32_t r0, r1, r2, r3;
                ldsm_x4(r0, r1, r2, r3, sb + T_BHI + off);
                bh[np * 2][0] = r0; bh[np * 2][1] = r2;
                bh[np * 2 + 1][0] = r1; bh[np * 2 + 1][1] = r3;
                ldsm_x4(r0, r1, r2, r3, sb + T_BLO + off);
                bl[np * 2][0] = r0; bl[np * 2][1] = r2;
                bl[np * 2 + 1][0] = r1; bl[np * 2 + 1][1] = r3;
            }
#pragma unroll
            for (int mt = 0; mt < 2; mt++)
#pragma unroll
                for (int nt = 0; nt < 8; nt++) {
                    mma_bf16(acc[mt][nt], ah[mt], bh[nt]);   // hi*hi
                    mma_bf16(acc[mt][nt], ah[mt], bl[nt]);   // hi*lo
                    mma_bf16(acc[mt][nt], al[mt], bh[nt]);   // lo*hi
                }
        }
        __syncthreads();
    }

    // Epilogue: D-fragment mapping for m16n8: c0,c1 -> (row=lane/4, col=(lane%4)*2),
    // c2,c3 -> row+8.
    const int trow = lane >> 2;
    const int tcol = (lane & 3) * 2;
#pragma unroll
    for (int mt = 0; mt < 2; mt++) {
        const int grow = bm + wm + mt * 16 + trow;
#pragma unroll
        for (int nt = 0; nt < 8; nt++) {
            const int gcol = bn + wn + nt * 8 + tcol;
            float b0 = bias[gcol], b1 = bias[gcol + 1];
            float2 o0 = {acc[mt][nt][0] + b0, acc[mt][nt][1] + b1};
            float2 o1 = {acc[mt][nt][2] + b0, acc[mt][nt][3] + b1};
            *(float2*)(C + (size_t)grow * N + gcol)       = o0;
            *(float2*)(C + (size_t)(grow + 8) * N + gcol) = o1;
        }
    }
}

// ---------------------------------------------------------------------------
// Causal flash attention, fp32 (unchanged from R1)
// ---------------------------------------------------------------------------
#define QT 64
#define KT 64
#define RPW 8
#define KSTRIDE 68

__device__ __forceinline__ float warp_max(float v) {
#pragma unroll
    for (int off = 16; off; off >>= 1)
        v = fmaxf(v, __shfl_xor_sync(0xFFFFFFFFu, v, off));
    return v;
}
__device__ __forceinline__ float warp_sum(float v) {
#pragma unroll
    for (int off = 16; off; off >>= 1)
        v += __shfl_xor_sync(0xFFFFFFFFu, v, off);
    return v;
}

__global__ __launch_bounds__(256) void flash_fp32(
    const float* __restrict__ qkv, float* __restrict__ ctx, int T, int B)
{
    extern __shared__ float sm[];
    float* Qs = sm;
    float* Ks = Qs + QT * 64;
    float* Vs = Ks + KT * KSTRIDE;
    float* Ps = Vs + KT * 64;

    const int qt = blockIdx.x;
    const int bh = blockIdx.y;
    const int b  = bh >> 4;
    const int h  = bh & 15;

    const int tid  = threadIdx.x;
    const int w    = tid >> 5;
    const int lane = tid & 31;
    const int t0   = qt * QT;

    const size_t rowstride = (size_t)B * 3 * D_MODEL;
    const float* qbase = qkv + ((size_t)t0 * B + b) * (3 * D_MODEL) + h * HEAD_DIM;
    const float* kbase = qkv + (size_t)b * (3 * D_MODEL) + D_MODEL + h * HEAD_DIM;
    const float* vbase = kbase + D_MODEL;

    for (int i = tid; i < QT * 16; i += 256) {
        int r = i >> 4, d4 = (i & 15) * 4;
        float4 v = *(const float4*)(qbase + (size_t)r * rowstride + d4);
        v.x *= 0.125f; v.y *= 0.125f; v.z *= 0.125f; v.w *= 0.125f;
        *(float4*)(&Qs[r * 64 + d4]) = v;
    }

    float m[RPW], l[RPW], acc0[RPW], acc1[RPW];
#pragma unroll
    for (int r = 0; r < RPW; r++) {
        m[r] = -1e30f; l[r] = 0.f; acc0[r] = 0.f; acc1[r] = 0.f;
    }

    for (int kt = 0; kt <= qt; kt++) {
        __syncthreads();
        const int kt0 = kt * KT;
        for (int i = tid; i < KT * 16; i += 256) {
            int r = i >> 4, d4 = (i & 15) * 4;
            const float* kp = kbase + ((size_t)(kt0 + r)) * rowstride + d4;
            const float* vp = vbase + ((size_t)(kt0 + r)) * rowstride + d4;
            *(float4*)(&Ks[r * KSTRIDE + d4]) = *(const float4*)kp;
            *(float4*)(&Vs[r * 64 + d4])      = *(const float4*)vp;
        }
        __syncthreads();

        const bool diag = (kt == qt);
        float* pw = &Ps[w * (RPW * 64)];

#pragma unroll
        for (int r = 0; r < RPW; r++) {
            const int row = w * RPW + r;
            const float* qrow = &Qs[row * 64];
            const float* k0p = &Ks[lane * KSTRIDE];
            const float* k1p = &Ks[(lane + 32) * KSTRIDE];
            float s0 = 0.f, s1 = 0.f;
#pragma unroll
            for (int d4 = 0; d4 < 16; d4++) {
                float4 q  = *(const float4*)(qrow + d4 * 4);
                float4 ka = *(const float4*)(k0p + d4 * 4);
                float4 kb = *(const float4*)(k1p + d4 * 4);
                s0 += q.x * ka.x + q.y * ka.y + q.z * ka.z + q.w * ka.w;
                s1 += q.x * kb.x + q.y * kb.y + q.z * kb.z + q.w * kb.w;
            }
            if (diag) {
                if (lane > row)      s0 = -1e30f;
                if (lane + 32 > row) s1 = -1e30f;
            }
            float tm = warp_max(fmaxf(s0, s1));
            float mnew = fmaxf(m[r], tm);
            float p0 = __expf(s0 - mnew);
            float p1 = __expf(s1 - mnew);
            float rs = warp_sum(p0 + p1);
            float alpha = __expf(m[r] - mnew);
            l[r] = l[r] * alpha + rs;
            acc0[r] *= alpha;
            acc1[r] *= alpha;
            m[r] = mnew;
            pw[r * 64 + lane]      = p0;
            pw[r * 64 + lane + 32] = p1;
        }
        __syncwarp();

#pragma unroll 4
        for (int k = 0; k < KT; k++) {
            float v0 = Vs[k * 64 + lane];
            float v1 = Vs[k * 64 + lane + 32];
#pragma unroll
            for (int r = 0; r < RPW; r++) {
                float p = pw[r * 64 + k];
                acc0[r] += p * v0;
                acc1[r] += p * v1;
            }
        }
        __syncwarp();
    }

#pragma unroll
    for (int r = 0; r < RPW; r++) {
        const int row = w * RPW + r;
        const float inv = 1.f / l[r];
        size_t o = ((size_t)(t0 + row) * B + b) * D_MODEL + h * HEAD_DIM;
        ctx[o + lane]      = acc0[r] * inv;
        ctx[o + lane + 32] = acc1[r] * inv;
    }
}

// ---------------------------------------------------------------------------
extern "C" void kernel_launch(void* const* d_in, const int* in_sizes, int n_in,
                              void* d_out, int out_size)
{
    const float* x    = (const float*)d_in[0];
    const float* Wqkv = (const float*)d_in[1];
    const float* bqkv = (const float*)d_in[2];
    const float* Wout = (const float*)d_in[3];
    const float* bout = (const float*)d_in[4];
    float* out = (float*)d_out;

    const int B = 2;
    const int M = in_sizes[0] / D_MODEL;   // 4096
    const int T = M / B;                   // 2048

    float *qkv, *ctx;
    __nv_bfloat16 *xhi, *xlo, *w1hi, *w1lo, *w2hi, *w2lo, *chi, *clo;
    cudaGetSymbolAddress((void**)&qkv, g_qkv);
    cudaGetSymbolAddress((void**)&ctx, g_ctx);
    cudaGetSymbolAddress((void**)&xhi, g_xhi);
    cudaGetSymbolAddress((void**)&xlo, g_xlo);
    cudaGetSymbolAddress((void**)&w1hi, g_w1hi);
    cudaGetSymbolAddress((void**)&w1lo, g_w1lo);
    cudaGetSymbolAddress((void**)&w2hi, g_w2hi);
    cudaGetSymbolAddress((void**)&w2lo, g_w2lo);
    cudaGetSymbolAddress((void**)&chi, g_chi);
    cudaGetSymbolAddress((void**)&clo, g_clo);

    cudaFuncSetAttribute(gemm_mma, cudaFuncAttributeMaxDynamicSharedMemorySize, GSMEM_TOTAL);

    // Split x and Wqkv^T, then QKV projection on tensor cores
    split_convert<<<(M * D_MODEL / 4 + 255) / 256, 256>>>(x, xhi, xlo, M * D_MODEL / 4);
    split_convert_T<<<dim3(3 * D_MODEL / 32, D_MODEL / 32), dim3(32, 8)>>>(
        Wqkv, w1hi, w1lo, D_MODEL, 3 * D_MODEL);
    gemm_mma<<<dim3(3 * D_MODEL / 128, M / 128), 256, GSMEM_TOTAL>>>(
        xhi, xlo, w1hi, w1lo, bqkv, qkv, M, 3 * D_MODEL, D_MODEL);

    // Causal flash attention (fp32)
    const size_t smem = (QT * 64 + KT * KSTRIDE + KT * 64 + 8 * RPW * 64) * sizeof(float);
    cudaFuncSetAttribute(flash_fp32, cudaFuncAttributeMaxDynamicSharedMemorySize, (int)smem);
    flash_fp32<<<dim3(T / QT, B * N_HEADS), 256, smem>>>(qkv, ctx, T, B);

    // Split ctx and Wout^T, then output projection on tensor cores
    split_convert<<<(M * D_MODEL / 4 + 255) / 256, 256>>>(ctx, chi, clo, M * D_MODEL / 4);
    split_convert_T<<<dim3(D_MODEL / 32, D_MODEL / 32), dim3(32, 8)>>>(
        Wout, w2hi, w2lo, D_MODEL, D_MODEL);
    gemm_mma<<<dim3(D_MODEL / 128, M / 128), 256, GSMEM_TOTAL>>>(
        chi, clo, w2hi, w2lo, bout, out, M, D_MODEL, D_MODEL);
}

// round 4
// speedup vs baseline: 2.9860x; 2.3661x over previous
#include <cuda_runtime.h>
#include <cuda_bf16.h>
#include <cstdint>
#include <math.h>

#define D_MODEL 1024
#define N_HEADS 16
#define HEAD_DIM 64
#define BATCH 2
#define SEQ 2048

// ---------------------------------------------------------------------------
// Scratch (allocation-free rule: __device__ globals)
// ---------------------------------------------------------------------------
__device__ __nv_bfloat16 g_xhi[4096 * 1024];        // x split
__device__ __nv_bfloat16 g_xlo[4096 * 1024];
__device__ __nv_bfloat16 g_w1hi[3072 * 1024];       // Wqkv^T split  [N,K]
__device__ __nv_bfloat16 g_w1lo[3072 * 1024];
__device__ __nv_bfloat16 g_w2hi[1024 * 1024];       // Wout^T split  [N,K]
__device__ __nv_bfloat16 g_w2lo[1024 * 1024];
// q/k/v in [B,H,T,64] split bf16 (q prescaled by 0.125)
__device__ __nv_bfloat16 g_qhi[BATCH * N_HEADS * SEQ * 64];
__device__ __nv_bfloat16 g_qlo[BATCH * N_HEADS * SEQ * 64];
__device__ __nv_bfloat16 g_khi[BATCH * N_HEADS * SEQ * 64];
__device__ __nv_bfloat16 g_klo[BATCH * N_HEADS * SEQ * 64];
__device__ __nv_bfloat16 g_vhi[BATCH * N_HEADS * SEQ * 64];
__device__ __nv_bfloat16 g_vlo[BATCH * N_HEADS * SEQ * 64];
// attention output (ctx) split bf16, [m=T*B rows][1024]
__device__ __nv_bfloat16 g_chi[4096 * 1024];
__device__ __nv_bfloat16 g_clo[4096 * 1024];

// ---------------------------------------------------------------------------
// PTX helpers (plain sm_103-compatible: mma.sync / ldmatrix / cp.async)
// ---------------------------------------------------------------------------
__device__ __forceinline__ uint32_t smem_to_u32(const void* p) {
    uint32_t a;
    asm("{ .reg .u64 t; cvta.to.shared.u64 t, %1; cvt.u32.u64 %0, t; }" : "=r"(a) : "l"(p));
    return a;
}
__device__ __forceinline__ void cp_async16(uint32_t dst, const void* src) {
    asm volatile("cp.async.ca.shared.global [%0], [%1], 16;" :: "r"(dst), "l"(src) : "memory");
}
#define CP_COMMIT() asm volatile("cp.async.commit_group;" ::: "memory")
#define CP_WAIT(n)  asm volatile("cp.async.wait_group %0;" :: "n"(n) : "memory")

__device__ __forceinline__ void ldsm_x4(uint32_t& r0, uint32_t& r1, uint32_t& r2, uint32_t& r3,
                                        uint32_t addr) {
    asm volatile("ldmatrix.sync.aligned.m8n8.x4.shared.b16 {%0,%1,%2,%3}, [%4];"
                 : "=r"(r0), "=r"(r1), "=r"(r2), "=r"(r3) : "r"(addr));
}
__device__ __forceinline__ void ldsm_x4_t(uint32_t& r0, uint32_t& r1, uint32_t& r2, uint32_t& r3,
                                          uint32_t addr) {
    asm volatile("ldmatrix.sync.aligned.m8n8.x4.trans.shared.b16 {%0,%1,%2,%3}, [%4];"
                 : "=r"(r0), "=r"(r1), "=r"(r2), "=r"(r3) : "r"(addr));
}
__device__ __forceinline__ void mma_bf16(float c[4], const uint32_t a[4], const uint32_t b[2]) {
    asm volatile(
        "mma.sync.aligned.m16n8k16.row.col.f32.bf16.bf16.f32 "
        "{%0,%1,%2,%3}, {%4,%5,%6,%7}, {%8,%9}, {%0,%1,%2,%3};"
        : "+f"(c[0]), "+f"(c[1]), "+f"(c[2]), "+f"(c[3])
        : "r"(a[0]), "r"(a[1]), "r"(a[2]), "r"(a[3]), "r"(b[0]), "r"(b[1]));
}

__device__ __forceinline__ void split2(float x, float y, uint32_t& hi, uint32_t& lo) {
    __nv_bfloat16 hx = __float2bfloat16(x), hy = __float2bfloat16(y);
    __nv_bfloat162 h2 = __halves2bfloat162(hx, hy);
    __nv_bfloat162 l2 = __halves2bfloat162(
        __float2bfloat16(x - __bfloat162float(hx)),
        __float2bfloat16(y - __bfloat162float(hy)));
    hi = *(uint32_t*)&h2;
    lo = *(uint32_t*)&l2;
}

// ---------------------------------------------------------------------------
// Split-precision conversion kernels
// ---------------------------------------------------------------------------
__global__ __launch_bounds__(256) void split_convert(
    const float* __restrict__ in, __nv_bfloat16* __restrict__ hi,
    __nv_bfloat16* __restrict__ lo, int n4)
{
    int i = blockIdx.x * blockDim.x + threadIdx.x;
    if (i >= n4) return;
    float4 v = ((const float4*)in)[i];
    __nv_bfloat16 h0 = __float2bfloat16(v.x);
    __nv_bfloat16 h1 = __float2bfloat16(v.y);
    __nv_bfloat16 h2 = __float2bfloat16(v.z);
    __nv_bfloat16 h3 = __float2bfloat16(v.w);
    __nv_bfloat16 l0 = __float2bfloat16(v.x - __bfloat162float(h0));
    __nv_bfloat16 l1 = __float2bfloat16(v.y - __bfloat162float(h1));
    __nv_bfloat16 l2 = __float2bfloat16(v.z - __bfloat162float(h2));
    __nv_bfloat16 l3 = __float2bfloat16(v.w - __bfloat162float(h3));
    ((__nv_bfloat162*)hi)[i * 2]     = __halves2bfloat162(h0, h1);
    ((__nv_bfloat162*)hi)[i * 2 + 1] = __halves2bfloat162(h2, h3);
    ((__nv_bfloat162*)lo)[i * 2]     = __halves2bfloat162(l0, l1);
    ((__nv_bfloat162*)lo)[i * 2 + 1] = __halves2bfloat162(l2, l3);
}

// W[K,N] fp32 -> Wt_hi/Wt_lo [N,K] bf16 (transpose + split). 32x32 tiles.
__global__ __launch_bounds__(256) void split_convert_T(
    const float* __restrict__ W, __nv_bfloat16* __restrict__ hi,
    __nv_bfloat16* __restrict__ lo, int K, int N)
{
    __shared__ float t[32][33];
    const int n0 = blockIdx.x * 32;
    const int k0 = blockIdx.y * 32;
#pragma unroll
    for (int i = 0; i < 4; i++) {
        int k = k0 + threadIdx.y + i * 8;
        t[threadIdx.y + i * 8][threadIdx.x] = W[(size_t)k * N + n0 + threadIdx.x];
    }
    __syncthreads();
#pragma unroll
    for (int i = 0; i < 4; i++) {
        int nn = n0 + threadIdx.y + i * 8;
        float v = t[threadIdx.x][threadIdx.y + i * 8];
        __nv_bfloat16 h = __float2bfloat16(v);
        float r = v - __bfloat162float(h);
        hi[(size_t)nn * K + k0 + threadIdx.x] = h;
        lo[(size_t)nn * K + k0 + threadIdx.x] = __float2bfloat16(r);
    }
}

// ---------------------------------------------------------------------------
// HMMA bf16-split GEMM: C = A[M,K] @ Bt[N,K]^T + bias
// MODE 0: write fp32 C. MODE 1: QKV epilogue -> split bf16 q/k/v [B,H,T,64],
//         q prescaled by 0.125.
// ---------------------------------------------------------------------------
#define BK 32
#define ASTRIDE 40                     // bf16 elems per smem row (32 + 8 pad)
#define TILE_BYTES (128 * ASTRIDE * 2) // 10240
#define T_AHI 0
#define T_ALO (1 * TILE_BYTES)
#define T_BHI (2 * TILE_BYTES)
#define T_BLO (3 * TILE_BYTES)
#define STAGE_BYTES (4 * TILE_BYTES)   // 40960
#define STAGES 3
#define GSMEM_TOTAL (STAGES * STAGE_BYTES)  // 122880

template <int MODE>
__global__ __launch_bounds__(256, 1) void gemm_mma(
    const __nv_bfloat16* __restrict__ Ahi, const __nv_bfloat16* __restrict__ Alo,
    const __nv_bfloat16* __restrict__ Bhi, const __nv_bfloat16* __restrict__ Blo,
    const float* __restrict__ bias, float* __restrict__ C,
    __nv_bfloat16* __restrict__ qhi, __nv_bfloat16* __restrict__ qlo,
    __nv_bfloat16* __restrict__ khi, __nv_bfloat16* __restrict__ klo,
    __nv_bfloat16* __restrict__ vhi, __nv_bfloat16* __restrict__ vlo,
    int M, int N, int K)
{
    extern __shared__ char smem[];
    const uint32_t smem_base = smem_to_u32(smem);
    const int tid  = threadIdx.x;
    const int wid  = tid >> 5;
    const int lane = tid & 31;
    const int bm = blockIdx.y * 128;
    const int bn = blockIdx.x * 128;
    const int wm = (wid & 3) * 32;
    const int wn = (wid >> 2) * 64;

    const __nv_bfloat16* srcs[4]  = {Ahi, Alo, Bhi, Blo};
    const int rows0[4]            = {bm, bm, bn, bn};

    auto load_stage = [&](int it) {
        const uint32_t sb = smem_base + (it % STAGES) * STAGE_BYTES;
        const int k0 = it * BK;
#pragma unroll
        for (int c = tid; c < 2048; c += 256) {
            int mat = c >> 9;
            int r   = (c >> 2) & 127;
            int kc  = (c & 3) * 8;
            const __nv_bfloat16* src = srcs[mat] + (size_t)(rows0[mat] + r) * K + k0 + kc;
            uint32_t dst = sb + mat * TILE_BYTES + (r * ASTRIDE + kc) * 2;
            cp_async16(dst, src);
        }
    };

    const int NK = K / BK;
    load_stage(0); CP_COMMIT();
    load_stage(1); CP_COMMIT();

    float acc[2][8][4];
#pragma unroll
    for (int mt = 0; mt < 2; mt++)
#pragma unroll
        for (int nt = 0; nt < 8; nt++)
#pragma unroll
            for (int i = 0; i < 4; i++) acc[mt][nt][i] = 0.f;

    const int lrow = lane & 15;
    const int lcol = (lane >> 4) * 8;

    for (int kt = 0; kt < NK; kt++) {
        CP_WAIT(STAGES - 2);
        __syncthreads();
        if (kt + STAGES - 1 < NK) load_stage(kt + STAGES - 1);
        CP_COMMIT();
        const uint32_t sb = smem_base + (kt % STAGES) * STAGE_BYTES;

#pragma unroll
        for (int ks = 0; ks < 2; ks++) {
            uint32_t ah[2][4], al[2][4];
#pragma unroll
            for (int mt = 0; mt < 2; mt++) {
                uint32_t off = ((wm + mt * 16 + lrow) * ASTRIDE + ks * 16 + lcol) * 2;
                ldsm_x4(ah[mt][0], ah[mt][1], ah[mt][2], ah[mt][3], sb + T_AHI + off);
                ldsm_x4(al[mt][0], al[mt][1], al[mt][2], al[mt][3], sb + T_ALO + off);
            }
            uint32_t bh[8][2], bl[8][2];
#pragma unroll
            for (int np = 0; np < 4; np++) {
                uint32_t off = ((wn + np * 16 + lrow) * ASTRIDE + ks * 16 + lcol) * 2;
                uint32_t r0, r1, r2, r3;
                ldsm_x4(r0, r1, r2, r3, sb + T_BHI + off);
                bh[np * 2][0] = r0; bh[np * 2][1] = r2;
                bh[np * 2 + 1][0] = r1; bh[np * 2 + 1][1] = r3;
                ldsm_x4(r0, r1, r2, r3, sb + T_BLO + off);
                bl[np * 2][0] = r0; bl[np * 2][1] = r2;
                bl[np * 2 + 1][0] = r1; bl[np * 2 + 1][1] = r3;
            }
#pragma unroll
            for (int mt = 0; mt < 2; mt++)
#pragma unroll
                for (int nt = 0; nt < 8; nt++) {
                    mma_bf16(acc[mt][nt], ah[mt], bh[nt]);
                    mma_bf16(acc[mt][nt], ah[mt], bl[nt]);
                    mma_bf16(acc[mt][nt], al[mt], bh[nt]);
                }
        }
        __syncthreads();
    }

    const int trow = lane >> 2;
    const int tcol = (lane & 3) * 2;

    if (MODE == 0) {
#pragma unroll
        for (int mt = 0; mt < 2; mt++) {
            const int grow = bm + wm + mt * 16 + trow;
#pragma unroll
            for (int nt = 0; nt < 8; nt++) {
                const int gcol = bn + wn + nt * 8 + tcol;
                float b0 = bias[gcol], b1 = bias[gcol + 1];
                float2 o0 = {acc[mt][nt][0] + b0, acc[mt][nt][1] + b1};
                float2 o1 = {acc[mt][nt][2] + b0, acc[mt][nt][3] + b1};
                *(float2*)(C + (size_t)grow * N + gcol)       = o0;
                *(float2*)(C + (size_t)(grow + 8) * N + gcol) = o1;
            }
        }
    } else {
        // sec uniform per CTA: bn multiple of 128, 1024 % 128 == 0
        const int sec = bn >> 10;
        __nv_bfloat16* dhi = (sec == 0) ? qhi : (sec == 1) ? khi : vhi;
        __nv_bfloat16* dlo = (sec == 0) ? qlo : (sec == 1) ? klo : vlo;
        const float scl = (sec == 0) ? 0.125f : 1.f;
#pragma unroll
        for (int mt = 0; mt < 2; mt++) {
            const int grow = bm + wm + mt * 16 + trow;
#pragma unroll
            for (int nt = 0; nt < 8; nt++) {
                const int gcol = bn + wn + nt * 8 + tcol;
                const int hh = (gcol >> 6) & 15;
                const int dd = gcol & 63;
                float b0 = bias[gcol], b1 = bias[gcol + 1];
#pragma unroll
                for (int rr = 0; rr < 2; rr++) {
                    int row = grow + rr * 8;
                    int t = row >> 1, b_ = row & 1;
                    size_t idx = (((size_t)(b_ * 16 + hh)) * SEQ + t) * 64 + dd;
                    float v0 = (acc[mt][nt][rr * 2]     + b0) * scl;
                    float v1 = (acc[mt][nt][rr * 2 + 1] + b1) * scl;
                    uint32_t hi, lo;
                    split2(v0, v1, hi, lo);
                    *(uint32_t*)(dhi + idx) = hi;
                    *(uint32_t*)(dlo + idx) = lo;
                }
            }
        }
    }
}

// ---------------------------------------------------------------------------
// Flash attention on HMMA, split-bf16 everywhere, fp32 softmax.
// CTA: 128 queries x one (b,h). 8 warps x 16 rows. 64-key tiles, 2-stage
// cp.async pipeline. Q resident in smem. Output: split bf16 ctx [m][1024].
// ---------------------------------------------------------------------------
#define FAST 72                        // smem row stride in bf16 elems (144 B)
#define FQ_HI 0
#define FQ_LO 18432
#define FKV_O 36864
#define FKV_STAGE 36864                // khi 0 | klo 9216 | vhi 18432 | vlo 27648
#define FSMEM_TOTAL (FKV_O + 2 * FKV_STAGE)  // 110592

__global__ __launch_bounds__(256, 1) void flash_mma(
    const __nv_bfloat16* __restrict__ qhi, const __nv_bfloat16* __restrict__ qlo,
    const __nv_bfloat16* __restrict__ khi, const __nv_bfloat16* __restrict__ klo,
    const __nv_bfloat16* __restrict__ vhi, const __nv_bfloat16* __restrict__ vlo,
    __nv_bfloat16* __restrict__ chi, __nv_bfloat16* __restrict__ clo,
    int nqt)
{
    extern __shared__ char smem[];
    const uint32_t sb = smem_to_u32(smem);
    const int tid  = threadIdx.x;
    const int wid  = tid >> 5;
    const int lane = tid & 31;

    const int bx = blockIdx.x;
    const int bh = bx & 31;                 // b*16 + h
    const int qt = nqt - 1 - (bx >> 5);     // big tiles first
    const int b_ = bh >> 4;
    const int h  = bh & 15;
    const int t0 = qt * 128;
    const int nkt = 2 * (qt + 1);
    const size_t hb = ((size_t)(b_ * 16 + h)) * SEQ * 64;

    // Q tiles (hi, lo): 128 rows x 64 elems, 8 chunks/row
#pragma unroll
    for (int c = tid; c < 2048; c += 256) {
        int tile = c >> 10, r = (c >> 3) & 127, ck = c & 7;
        const __nv_bfloat16* src = (tile ? qlo : qhi) + hb + (size_t)(t0 + r) * 64 + ck * 8;
        cp_async16(sb + (tile ? FQ_LO : FQ_HI) + r * 144 + ck * 16, src);
    }
    const __nv_bfloat16* kvsrc[4] = {khi, klo, vhi, vlo};
    auto load_kv = [&](int kt) {
        uint32_t st = sb + FKV_O + (kt & 1) * FKV_STAGE;
        int kt0 = kt * 64;
#pragma unroll
        for (int c = tid; c < 2048; c += 256) {
            int tile = c >> 9, r = (c >> 3) & 63, ck = c & 7;
            cp_async16(st + tile * 9216 + r * 144 + ck * 16,
                       kvsrc[tile] + hb + (size_t)(kt0 + r) * 64 + ck * 8);
        }
    };
    load_kv(0); CP_COMMIT();
    if (nkt > 1) { load_kv(1); CP_COMMIT(); }

    float o[8][4];
#pragma unroll
    for (int nt = 0; nt < 8; nt++)
#pragma unroll
        for (int i = 0; i < 4; i++) o[nt][i] = 0.f;
    float m0 = -1e30f, m1 = -1e30f, l0 = 0.f, l1 = 0.f;

    const int lrow = lane & 15;
    const int lcol = (lane >> 4) * 8;
    const int g    = lane >> 2;
    const int tig  = lane & 3;
    const int wq0  = wid * 16;
    const int row0 = t0 + wq0 + g;
    const int row1 = row0 + 8;

    for (int kt = 0; kt < nkt; kt++) {
        if (kt < nkt - 1) { CP_WAIT(1); } else { CP_WAIT(0); }
        __syncthreads();
        const int kt0 = kt * 64;
        const uint32_t st = sb + FKV_O + (kt & 1) * FKV_STAGE;

        if (kt0 <= t0 + wq0 + 15) {        // warp has unmasked work
            // ---- S = Q @ K^T (split 3-MMA) ----
            float s[8][4];
#pragma unroll
            for (int nt = 0; nt < 8; nt++)
#pragma unroll
                for (int i = 0; i < 4; i++) s[nt][i] = 0.f;

#pragma unroll
            for (int ks = 0; ks < 4; ks++) {
                uint32_t ah[4], al[4];
                uint32_t qoff = (wq0 + lrow) * 144 + ks * 32 + lcol * 2;
                ldsm_x4(ah[0], ah[1], ah[2], ah[3], sb + FQ_HI + qoff);
                ldsm_x4(al[0], al[1], al[2], al[3], sb + FQ_LO + qoff);
                uint32_t bkh[8][2], bkl[8][2];
#pragma unroll
                for (int np = 0; np < 4; np++) {
                    uint32_t koff = (np * 16 + lrow) * 144 + ks * 32 + lcol * 2;
                    uint32_t r0, r1, r2, r3;
                    ldsm_x4(r0, r1, r2, r3, st + koff);
                    bkh[np * 2][0] = r0; bkh[np * 2][1] = r2;
                    bkh[np * 2 + 1][0] = r1; bkh[np * 2 + 1][1] = r3;
                    ldsm_x4(r0, r1, r2, r3, st + 9216 + koff);
                    bkl[np * 2][0] = r0; bkl[np * 2][1] = r2;
                    bkl[np * 2 + 1][0] = r1; bkl[np * 2 + 1][1] = r3;
                }
#pragma unroll
                for (int nt = 0; nt < 8; nt++) {
                    mma_bf16(s[nt], ah, bkh[nt]);
                    mma_bf16(s[nt], ah, bkl[nt]);
                    mma_bf16(s[nt], al, bkh[nt]);
                }
            }

            // ---- causal mask (diagonal band only) ----
            if (kt0 + 63 > t0 + wq0) {
#pragma unroll
                for (int nt = 0; nt < 8; nt++) {
                    int col = kt0 + nt * 8 + tig * 2;
                    if (col     > row0) s[nt][0] = -1e30f;
                    if (col + 1 > row0) s[nt][1] = -1e30f;
                    if (col     > row1) s[nt][2] = -1e30f;
                    if (col + 1 > row1) s[nt][3] = -1e30f;
                }
            }

            // ---- online softmax (fp32) ----
            float mx0 = -1e30f, mx1 = -1e30f;
#pragma unroll
            for (int nt = 0; nt < 8; nt++) {
                mx0 = fmaxf(mx0, fmaxf(s[nt][0], s[nt][1]));
                mx1 = fmaxf(mx1, fmaxf(s[nt][2], s[nt][3]));
            }
#pragma unroll
            for (int off = 1; off < 4; off <<= 1) {
                mx0 = fmaxf(mx0, __shfl_xor_sync(0xFFFFFFFFu, mx0, off));
                mx1 = fmaxf(mx1, __shfl_xor_sync(0xFFFFFFFFu, mx1, off));
            }
            float nm0 = fmaxf(m0, mx0), nm1 = fmaxf(m1, mx1);
            float a0 = __expf(m0 - nm0), a1 = __expf(m1 - nm1);
            float sum0 = 0.f, sum1 = 0.f;
#pragma unroll
            for (int nt = 0; nt < 8; nt++) {
                s[nt][0] = __expf(s[nt][0] - nm0);
                s[nt][1] = __expf(s[nt][1] - nm0);
                s[nt][2] = __expf(s[nt][2] - nm1);
                s[nt][3] = __expf(s[nt][3] - nm1);
                sum0 += s[nt][0] + s[nt][1];
                sum1 += s[nt][2] + s[nt][3];
            }
#pragma unroll
            for (int off = 1; off < 4; off <<= 1) {
                sum0 += __shfl_xor_sync(0xFFFFFFFFu, sum0, off);
                sum1 += __shfl_xor_sync(0xFFFFFFFFu, sum1, off);
            }
            l0 = l0 * a0 + sum0;
            l1 = l1 * a1 + sum1;
            m0 = nm0; m1 = nm1;
#pragma unroll
            for (int nt = 0; nt < 8; nt++) {
                o[nt][0] *= a0; o[nt][1] *= a0;
                o[nt][2] *= a1; o[nt][3] *= a1;
            }

            // ---- pack P fragments (split bf16) ----
            uint32_t ph[4][4], pl[4][4];
#pragma unroll
            for (int ks = 0; ks < 4; ks++) {
                split2(s[2 * ks][0],     s[2 * ks][1],     ph[ks][0], pl[ks][0]);
                split2(s[2 * ks][2],     s[2 * ks][3],     ph[ks][1], pl[ks][1]);
                split2(s[2 * ks + 1][0], s[2 * ks + 1][1], ph[ks][2], pl[ks][2]);
                split2(s[2 * ks + 1][2], s[2 * ks + 1][3], ph[ks][3], pl[ks][3]);
            }

            // ---- O += P @ V (split 3-MMA, V via ldmatrix.trans) ----
#pragma unroll
            for (int ks = 0; ks < 4; ks++) {
                uint32_t bvh[8][2], bvl[8][2];
#pragma unroll
                for (int db = 0; db < 4; db++) {
                    uint32_t voff = (ks * 16 + lrow) * 144 + db * 32 + lcol * 2;
                    uint32_t r0, r1, r2, r3;
                    ldsm_x4_t(r0, r1, r2, r3, st + 18432 + voff);
                    bvh[db * 2][0] = r0; bvh[db * 2][1] = r1;
                    bvh[db * 2 + 1][0] = r2; bvh[db * 2 + 1][1] = r3;
                    ldsm_x4_t(r0, r1, r2, r3, st + 27648 + voff);
                    bvl[db * 2][0] = r0; bvl[db * 2][1] = r1;
                    bvl[db * 2 + 1][0] = r2; bvl[db * 2 + 1][1] = r3;
                }
#pragma unroll
                for (int nt = 0; nt < 8; nt++) {
                    mma_bf16(o[nt], ph[ks], bvh[nt]);
                    mma_bf16(o[nt], ph[ks], bvl[nt]);
                    mma_bf16(o[nt], pl[ks], bvh[nt]);
                }
            }
        }
        __syncthreads();
        if (kt + 2 < nkt) { load_kv(kt + 2); CP_COMMIT(); }
    }

    // ---- epilogue: ctx split bf16, [m = t*B + b_][h*64 + d] ----
    const float i0 = 1.f / l0;
    const float i1 = 1.f / l1;
#pragma unroll
    for (int nt = 0; nt < 8; nt++) {
        const int d = nt * 8 + tig * 2;
        size_t o0 = ((size_t)(row0 * BATCH + b_)) * D_MODEL + h * 64 + d;
        size_t o1 = ((size_t)(row1 * BATCH + b_)) * D_MODEL + h * 64 + d;
        uint32_t hi, lo;
        split2(o[nt][0] * i0, o[nt][1] * i0, hi, lo);
        *(uint32_t*)(chi + o0) = hi;
        *(uint32_t*)(clo + o0) = lo;
        split2(o[nt][2] * i1, o[nt][3] * i1, hi, lo);
        *(uint32_t*)(chi + o1) = hi;
        *(uint32_t*)(clo + o1) = lo;
    }
}

// ---------------------------------------------------------------------------
extern "C" void kernel_launch(void* const* d_in, const int* in_sizes, int n_in,
                              void* d_out, int out_size)
{
    const float* x    = (const float*)d_in[0];
    const float* Wqkv = (const float*)d_in[1];
    const float* bqkv = (const float*)d_in[2];
    const float* Wout = (const float*)d_in[3];
    const float* bout = (const float*)d_in[4];
    float* out = (float*)d_out;

    const int M = in_sizes[0] / D_MODEL;   // 4096
    const int T = M / BATCH;               // 2048
    const int nqt = T / 128;               // 16

    __nv_bfloat16 *xhi, *xlo, *w1hi, *w1lo, *w2hi, *w2lo, *chi, *clo;
    __nv_bfloat16 *qhi, *qlo, *khi, *klo, *vhi, *vlo;
    cudaGetSymbolAddress((void**)&xhi, g_xhi);
    cudaGetSymbolAddress((void**)&xlo, g_xlo);
    cudaGetSymbolAddress((void**)&w1hi, g_w1hi);
    cudaGetSymbolAddress((void**)&w1lo, g_w1lo);
    cudaGetSymbolAddress((void**)&w2hi, g_w2hi);
    cudaGetSymbolAddress((void**)&w2lo, g_w2lo);
    cudaGetSymbolAddress((void**)&chi, g_chi);
    cudaGetSymbolAddress((void**)&clo, g_clo);
    cudaGetSymbolAddress((void**)&qhi, g_qhi);
    cudaGetSymbolAddress((void**)&qlo, g_qlo);
    cudaGetSymbolAddress((void**)&khi, g_khi);
    cudaGetSymbolAddress((void**)&klo, g_klo);
    cudaGetSymbolAddress((void**)&vhi, g_vhi);
    cudaGetSymbolAddress((void**)&vlo, g_vlo);

    cudaFuncSetAttribute(gemm_mma<0>, cudaFuncAttributeMaxDynamicSharedMemorySize, GSMEM_TOTAL);
    cudaFuncSetAttribute(gemm_mma<1>, cudaFuncAttributeMaxDynamicSharedMemorySize, GSMEM_TOTAL);
    cudaFuncSetAttribute(flash_mma, cudaFuncAttributeMaxDynamicSharedMemorySize, FSMEM_TOTAL);

    // 1) split inputs
    split_convert<<<(M * D_MODEL / 4 + 255) / 256, 256>>>(x, xhi, xlo, M * D_MODEL / 4);
    split_convert_T<<<dim3(3 * D_MODEL / 32, D_MODEL / 32), dim3(32, 8)>>>(
        Wqkv, w1hi, w1lo, D_MODEL, 3 * D_MODEL);

    // 2) QKV projection -> split bf16 q/k/v in [B,H,T,64]
    gemm_mma<1><<<dim3(3 * D_MODEL / 128, M / 128), 256, GSMEM_TOTAL>>>(
        xhi, xlo, w1hi, w1lo, bqkv, nullptr,
        qhi, qlo, khi, klo, vhi, vlo, M, 3 * D_MODEL, D_MODEL);

    // 3) causal flash attention on HMMA -> split bf16 ctx
    flash_mma<<<32 * nqt, 256, FSMEM_TOTAL>>>(qhi, qlo, khi, klo, vhi, vlo, chi, clo, nqt);

    // 4) output projection
    split_convert_T<<<dim3(D_MODEL / 32, D_MODEL / 32), dim3(32, 8)>>>(
        Wout, w2hi, w2lo, D_MODEL, D_MODEL);
    gemm_mma<0><<<dim3(D_MODEL / 128, M / 128), 256, GSMEM_TOTAL>>>(
        chi, clo, w2hi, w2lo, bout, out,
        nullptr, nullptr, nullptr, nullptr, nullptr, nullptr, M, D_MODEL, D_MODEL);
}

// round 5
// speedup vs baseline: 3.0489x; 1.0211x over previous
#include <cuda_runtime.h>
#include <cuda_bf16.h>
#include <cstdint>
#include <math.h>

#define D_MODEL 1024
#define N_HEADS 16
#define HEAD_DIM 64
#define BATCH 2
#define SEQ 2048

// ---------------------------------------------------------------------------
// Scratch (allocation-free rule: __device__ globals)
// ---------------------------------------------------------------------------
__device__ __nv_bfloat16 g_xhi[4096 * 1024];        // x split
__device__ __nv_bfloat16 g_xlo[4096 * 1024];
__device__ __nv_bfloat16 g_w1hi[3072 * 1024];       // Wqkv^T split  [N,K]
__device__ __nv_bfloat16 g_w1lo[3072 * 1024];
__device__ __nv_bfloat16 g_w2hi[1024 * 1024];       // Wout^T split  [N,K]
__device__ __nv_bfloat16 g_w2lo[1024 * 1024];
// q/k/v in [B,H,T,64] split bf16 (q prescaled by 0.125)
__device__ __nv_bfloat16 g_qhi[BATCH * N_HEADS * SEQ * 64];
__device__ __nv_bfloat16 g_qlo[BATCH * N_HEADS * SEQ * 64];
__device__ __nv_bfloat16 g_khi[BATCH * N_HEADS * SEQ * 64];
__device__ __nv_bfloat16 g_klo[BATCH * N_HEADS * SEQ * 64];
__device__ __nv_bfloat16 g_vhi[BATCH * N_HEADS * SEQ * 64];
__device__ __nv_bfloat16 g_vlo[BATCH * N_HEADS * SEQ * 64];
// attention output (ctx) split bf16, [m=T*B rows][1024]
__device__ __nv_bfloat16 g_chi[4096 * 1024];
__device__ __nv_bfloat16 g_clo[4096 * 1024];

// ---------------------------------------------------------------------------
// PTX helpers (plain sm_103-compatible: mma.sync / ldmatrix / cp.async)
// ---------------------------------------------------------------------------
__device__ __forceinline__ uint32_t smem_to_u32(const void* p) {
    uint32_t a;
    asm("{ .reg .u64 t; cvta.to.shared.u64 t, %1; cvt.u32.u64 %0, t; }" : "=r"(a) : "l"(p));
    return a;
}
__device__ __forceinline__ void cp_async16(uint32_t dst, const void* src) {
    asm volatile("cp.async.cg.shared.global [%0], [%1], 16;" :: "r"(dst), "l"(src) : "memory");
}
#define CP_COMMIT() asm volatile("cp.async.commit_group;" ::: "memory")
#define CP_WAIT(n)  asm volatile("cp.async.wait_group %0;" :: "n"(n) : "memory")

__device__ __forceinline__ void ldsm_x4(uint32_t& r0, uint32_t& r1, uint32_t& r2, uint32_t& r3,
                                        uint32_t addr) {
    asm volatile("ldmatrix.sync.aligned.m8n8.x4.shared.b16 {%0,%1,%2,%3}, [%4];"
                 : "=r"(r0), "=r"(r1), "=r"(r2), "=r"(r3) : "r"(addr));
}
__device__ __forceinline__ void ldsm_x4_t(uint32_t& r0, uint32_t& r1, uint32_t& r2, uint32_t& r3,
                                          uint32_t addr) {
    asm volatile("ldmatrix.sync.aligned.m8n8.x4.trans.shared.b16 {%0,%1,%2,%3}, [%4];"
                 : "=r"(r0), "=r"(r1), "=r"(r2), "=r"(r3) : "r"(addr));
}
__device__ __forceinline__ void mma_bf16(float c[4], const uint32_t a[4], const uint32_t b[2]) {
    asm volatile(
        "mma.sync.aligned.m16n8k16.row.col.f32.bf16.bf16.f32 "
        "{%0,%1,%2,%3}, {%4,%5,%6,%7}, {%8,%9}, {%0,%1,%2,%3};"
        : "+f"(c[0]), "+f"(c[1]), "+f"(c[2]), "+f"(c[3])
        : "r"(a[0]), "r"(a[1]), "r"(a[2]), "r"(a[3]), "r"(b[0]), "r"(b[1]));
}

__device__ __forceinline__ void split2(float x, float y, uint32_t& hi, uint32_t& lo) {
    __nv_bfloat16 hx = __float2bfloat16(x), hy = __float2bfloat16(y);
    __nv_bfloat162 h2 = __halves2bfloat162(hx, hy);
    __nv_bfloat162 l2 = __halves2bfloat162(
        __float2bfloat16(x - __bfloat162float(hx)),
        __float2bfloat16(y - __bfloat162float(hy)));
    hi = *(uint32_t*)&h2;
    lo = *(uint32_t*)&l2;
}

// ---------------------------------------------------------------------------
// Split-precision conversion kernels
// ---------------------------------------------------------------------------
__global__ __launch_bounds__(256) void split_convert(
    const float* __restrict__ in, __nv_bfloat16* __restrict__ hi,
    __nv_bfloat16* __restrict__ lo, int n4)
{
    int i = blockIdx.x * blockDim.x + threadIdx.x;
    if (i >= n4) return;
    float4 v = ((const float4*)in)[i];
    __nv_bfloat16 h0 = __float2bfloat16(v.x);
    __nv_bfloat16 h1 = __float2bfloat16(v.y);
    __nv_bfloat16 h2 = __float2bfloat16(v.z);
    __nv_bfloat16 h3 = __float2bfloat16(v.w);
    __nv_bfloat16 l0 = __float2bfloat16(v.x - __bfloat162float(h0));
    __nv_bfloat16 l1 = __float2bfloat16(v.y - __bfloat162float(h1));
    __nv_bfloat16 l2 = __float2bfloat16(v.z - __bfloat162float(h2));
    __nv_bfloat16 l3 = __float2bfloat16(v.w - __bfloat162float(h3));
    ((__nv_bfloat162*)hi)[i * 2]     = __halves2bfloat162(h0, h1);
    ((__nv_bfloat162*)hi)[i * 2 + 1] = __halves2bfloat162(h2, h3);
    ((__nv_bfloat162*)lo)[i * 2]     = __halves2bfloat162(l0, l1);
    ((__nv_bfloat162*)lo)[i * 2 + 1] = __halves2bfloat162(l2, l3);
}

// W[K,N] fp32 -> Wt_hi/Wt_lo [N,K] bf16 (transpose + split). 32x32 tiles.
__global__ __launch_bounds__(256) void split_convert_T(
    const float* __restrict__ W, __nv_bfloat16* __restrict__ hi,
    __nv_bfloat16* __restrict__ lo, int K, int N)
{
    __shared__ float t[32][33];
    const int n0 = blockIdx.x * 32;
    const int k0 = blockIdx.y * 32;
#pragma unroll
    for (int i = 0; i < 4; i++) {
        int k = k0 + threadIdx.y + i * 8;
        t[threadIdx.y + i * 8][threadIdx.x] = W[(size_t)k * N + n0 + threadIdx.x];
    }
    __syncthreads();
#pragma unroll
    for (int i = 0; i < 4; i++) {
        int nn = n0 + threadIdx.y + i * 8;
        float v = t[threadIdx.x][threadIdx.y + i * 8];
        __nv_bfloat16 h = __float2bfloat16(v);
        float r = v - __bfloat162float(h);
        hi[(size_t)nn * K + k0 + threadIdx.x] = h;
        lo[(size_t)nn * K + k0 + threadIdx.x] = __float2bfloat16(r);
    }
}

// ---------------------------------------------------------------------------
// HMMA bf16-split GEMM: C = A[M,K] @ Bt[N,K]^T + bias
// 2-stage cp.async pipeline, 2 CTAs/SM.
// MODE 0: write fp32 C. MODE 1: QKV epilogue -> split bf16 q/k/v [B,H,T,64].
// ---------------------------------------------------------------------------
#define BK 32
#define ASTRIDE 40                     // bf16 elems per smem row (32 + 8 pad)
#define TILE_BYTES (128 * ASTRIDE * 2) // 10240
#define T_AHI 0
#define T_ALO (1 * TILE_BYTES)
#define T_BHI (2 * TILE_BYTES)
#define T_BLO (3 * TILE_BYTES)
#define STAGE_BYTES (4 * TILE_BYTES)   // 40960
#define GSMEM_TOTAL (2 * STAGE_BYTES)  // 81920

template <int MODE>
__global__ __launch_bounds__(256, 2) void gemm_mma(
    const __nv_bfloat16* __restrict__ Ahi, const __nv_bfloat16* __restrict__ Alo,
    const __nv_bfloat16* __restrict__ Bhi, const __nv_bfloat16* __restrict__ Blo,
    const float* __restrict__ bias, float* __restrict__ C,
    __nv_bfloat16* __restrict__ qhi, __nv_bfloat16* __restrict__ qlo,
    __nv_bfloat16* __restrict__ khi, __nv_bfloat16* __restrict__ klo,
    __nv_bfloat16* __restrict__ vhi, __nv_bfloat16* __restrict__ vlo,
    int M, int N, int K)
{
    extern __shared__ char smem[];
    const uint32_t smem_base = smem_to_u32(smem);
    const int tid  = threadIdx.x;
    const int wid  = tid >> 5;
    const int lane = tid & 31;
    const int bm = blockIdx.y * 128;
    const int bn = blockIdx.x * 128;
    const int wm = (wid & 3) * 32;
    const int wn = (wid >> 2) * 64;

    const __nv_bfloat16* srcs[4]  = {Ahi, Alo, Bhi, Blo};
    const int rows0[4]            = {bm, bm, bn, bn};

    auto load_stage = [&](int it) {
        const uint32_t sb = smem_base + (it & 1) * STAGE_BYTES;
        const int k0 = it * BK;
#pragma unroll
        for (int c = tid; c < 2048; c += 256) {
            int mat = c >> 9;
            int r   = (c >> 2) & 127;
            int kc  = (c & 3) * 8;
            const __nv_bfloat16* src = srcs[mat] + (size_t)(rows0[mat] + r) * K + k0 + kc;
            uint32_t dst = sb + mat * TILE_BYTES + (r * ASTRIDE + kc) * 2;
            cp_async16(dst, src);
        }
    };

    const int NK = K / BK;
    load_stage(0); CP_COMMIT();

    float acc[2][8][4];
#pragma unroll
    for (int mt = 0; mt < 2; mt++)
#pragma unroll
        for (int nt = 0; nt < 8; nt++)
#pragma unroll
            for (int i = 0; i < 4; i++) acc[mt][nt][i] = 0.f;

    const int lrow = lane & 15;
    const int lcol = (lane >> 4) * 8;

    for (int kt = 0; kt < NK; kt++) {
        if (kt + 1 < NK) { load_stage(kt + 1); CP_COMMIT(); CP_WAIT(1); }
        else             { CP_WAIT(0); }
        __syncthreads();
        const uint32_t sb = smem_base + (kt & 1) * STAGE_BYTES;

#pragma unroll
        for (int ks = 0; ks < 2; ks++) {
            uint32_t ah[2][4], al[2][4];
#pragma unroll
            for (int mt = 0; mt < 2; mt++) {
                uint32_t off = ((wm + mt * 16 + lrow) * ASTRIDE + ks * 16 + lcol) * 2;
                ldsm_x4(ah[mt][0], ah[mt][1], ah[mt][2], ah[mt][3], sb + T_AHI + off);
                ldsm_x4(al[mt][0], al[mt][1], al[mt][2], al[mt][3], sb + T_ALO + off);
            }
            uint32_t bh[8][2], bl[8][2];
#pragma unroll
            for (int np = 0; np < 4; np++) {
                uint32_t off = ((wn + np * 16 + lrow) * ASTRIDE + ks * 16 + lcol) * 2;
                uint32_t r0, r1, r2, r3;
                ldsm_x4(r0, r1, r2, r3, sb + T_BHI + off);
                bh[np * 2][0] = r0; bh[np * 2][1] = r2;
                bh[np * 2 + 1][0] = r1; bh[np * 2 + 1][1] = r3;
                ldsm_x4(r0, r1, r2, r3, sb + T_BLO + off);
                bl[np * 2][0] = r0; bl[np * 2][1] = r2;
                bl[np * 2 + 1][0] = r1; bl[np * 2 + 1][1] = r3;
            }
#pragma unroll
            for (int mt = 0; mt < 2; mt++)
#pragma unroll
                for (int nt = 0; nt < 8; nt++) {
                    mma_bf16(acc[mt][nt], ah[mt], bh[nt]);
                    mma_bf16(acc[mt][nt], ah[mt], bl[nt]);
                    mma_bf16(acc[mt][nt], al[mt], bh[nt]);
                }
        }
        __syncthreads();
    }

    const int trow = lane >> 2;
    const int tcol = (lane & 3) * 2;

    if (MODE == 0) {
#pragma unroll
        for (int mt = 0; mt < 2; mt++) {
            const int grow = bm + wm + mt * 16 + trow;
#pragma unroll
            for (int nt = 0; nt < 8; nt++) {
                const int gcol = bn + wn + nt * 8 + tcol;
                float b0 = bias[gcol], b1 = bias[gcol + 1];
                float2 o0 = {acc[mt][nt][0] + b0, acc[mt][nt][1] + b1};
                float2 o1 = {acc[mt][nt][2] + b0, acc[mt][nt][3] + b1};
                *(float2*)(C + (size_t)grow * N + gcol)       = o0;
                *(float2*)(C + (size_t)(grow + 8) * N + gcol) = o1;
            }
        }
    } else {
        const int sec = bn >> 10;
        __nv_bfloat16* dhi = (sec == 0) ? qhi : (sec == 1) ? khi : vhi;
        __nv_bfloat16* dlo = (sec == 0) ? qlo : (sec == 1) ? klo : vlo;
        const float scl = (sec == 0) ? 0.125f : 1.f;
#pragma unroll
        for (int mt = 0; mt < 2; mt++) {
            const int grow = bm + wm + mt * 16 + trow;
#pragma unroll
            for (int nt = 0; nt < 8; nt++) {
                const int gcol = bn + wn + nt * 8 + tcol;
                const int hh = (gcol >> 6) & 15;
                const int dd = gcol & 63;
                float b0 = bias[gcol], b1 = bias[gcol + 1];
#pragma unroll
                for (int rr = 0; rr < 2; rr++) {
                    int row = grow + rr * 8;
                    int t = row >> 1, b_ = row & 1;
                    size_t idx = (((size_t)(b_ * 16 + hh)) * SEQ + t) * 64 + dd;
                    float v0 = (acc[mt][nt][rr * 2]     + b0) * scl;
                    float v1 = (acc[mt][nt][rr * 2 + 1] + b1) * scl;
                    uint32_t hi, lo;
                    split2(v0, v1, hi, lo);
                    *(uint32_t*)(dhi + idx) = hi;
                    *(uint32_t*)(dlo + idx) = lo;
                }
            }
        }
    }
}

// ---------------------------------------------------------------------------
// Flash attention on HMMA, split-bf16, fp32 softmax. 2 CTAs/SM.
// CTA: 128 queries x one (b,h). 8 warps x 16 rows. 64-key tiles, 2-stage
// cp.async pipeline. Q resident in smem. Output: split bf16 ctx [m][1024].
// ---------------------------------------------------------------------------
#define FQ_HI 0
#define FQ_LO 18432
#define FKV_O 36864
#define FKV_STAGE 36864                // khi 0 | klo 9216 | vhi 18432 | vlo 27648
#define FSMEM_TOTAL (FKV_O + 2 * FKV_STAGE)  // 110592

__global__ __launch_bounds__(256, 2) void flash_mma(
    const __nv_bfloat16* __restrict__ qhi, const __nv_bfloat16* __restrict__ qlo,
    const __nv_bfloat16* __restrict__ khi, const __nv_bfloat16* __restrict__ klo,
    const __nv_bfloat16* __restrict__ vhi, const __nv_bfloat16* __restrict__ vlo,
    __nv_bfloat16* __restrict__ chi, __nv_bfloat16* __restrict__ clo,
    int nqt)
{
    extern __shared__ char smem[];
    const uint32_t sb = smem_to_u32(smem);
    const int tid  = threadIdx.x;
    const int wid  = tid >> 5;
    const int lane = tid & 31;

    const int bx = blockIdx.x;
    const int bh = bx & 31;                 // b*16 + h
    const int qt = nqt - 1 - (bx >> 5);     // big tiles first
    const int b_ = bh >> 4;
    const int h  = bh & 15;
    const int t0 = qt * 128;
    const int nkt = 2 * (qt + 1);
    const size_t hb = ((size_t)(b_ * 16 + h)) * SEQ * 64;

#pragma unroll
    for (int c = tid; c < 2048; c += 256) {
        int tile = c >> 10, r = (c >> 3) & 127, ck = c & 7;
        const __nv_bfloat16* src = (tile ? qlo : qhi) + hb + (size_t)(t0 + r) * 64 + ck * 8;
        cp_async16(sb + (tile ? FQ_LO : FQ_HI) + r * 144 + ck * 16, src);
    }
    const __nv_bfloat16* kvsrc[4] = {khi, klo, vhi, vlo};
    auto load_kv = [&](int kt) {
        uint32_t st = sb + FKV_O + (kt & 1) * FKV_STAGE;
        int kt0 = kt * 64;
#pragma unroll
        for (int c = tid; c < 2048; c += 256) {
            int tile = c >> 9, r = (c >> 3) & 63, ck = c & 7;
            cp_async16(st + tile * 9216 + r * 144 + ck * 16,
                       kvsrc[tile] + hb + (size_t)(kt0 + r) * 64 + ck * 8);
        }
    };
    load_kv(0); CP_COMMIT();
    if (nkt > 1) { load_kv(1); CP_COMMIT(); }

    float o[8][4];
#pragma unroll
    for (int nt = 0; nt < 8; nt++)
#pragma unroll
        for (int i = 0; i < 4; i++) o[nt][i] = 0.f;
    float m0 = -1e30f, m1 = -1e30f, l0 = 0.f, l1 = 0.f;

    const int lrow = lane & 15;
    const int lcol = (lane >> 4) * 8;
    const int g    = lane >> 2;
    const int tig  = lane & 3;
    const int wq0  = wid * 16;
    const int row0 = t0 + wq0 + g;
    const int row1 = row0 + 8;

    for (int kt = 0; kt < nkt; kt++) {
        if (kt < nkt - 1) { CP_WAIT(1); } else { CP_WAIT(0); }
        __syncthreads();
        const int kt0 = kt * 64;
        const uint32_t st = sb + FKV_O + (kt & 1) * FKV_STAGE;

        if (kt0 <= t0 + wq0 + 15) {
            // ---- S = Q @ K^T (split 3-MMA) ----
            float s[8][4];
#pragma unroll
            for (int nt = 0; nt < 8; nt++)
#pragma unroll
                for (int i = 0; i < 4; i++) s[nt][i] = 0.f;

#pragma unroll
            for (int ks = 0; ks < 4; ks++) {
                uint32_t ah[4], al[4];
                uint32_t qoff = (wq0 + lrow) * 144 + ks * 32 + lcol * 2;
                ldsm_x4(ah[0], ah[1], ah[2], ah[3], sb + FQ_HI + qoff);
                ldsm_x4(al[0], al[1], al[2], al[3], sb + FQ_LO + qoff);
                uint32_t bkh[8][2], bkl[8][2];
#pragma unroll
                for (int np = 0; np < 4; np++) {
                    uint32_t koff = (np * 16 + lrow) * 144 + ks * 32 + lcol * 2;
                    uint32_t r0, r1, r2, r3;
                    ldsm_x4(r0, r1, r2, r3, st + koff);
                    bkh[np * 2][0] = r0; bkh[np * 2][1] = r2;
                    bkh[np * 2 + 1][0] = r1; bkh[np * 2 + 1][1] = r3;
                    ldsm_x4(r0, r1, r2, r3, st + 9216 + koff);
                    bkl[np * 2][0] = r0; bkl[np * 2][1] = r2;
                    bkl[np * 2 + 1][0] = r1; bkl[np * 2 + 1][1] = r3;
                }
#pragma unroll
                for (int nt = 0; nt < 8; nt++) {
                    mma_bf16(s[nt], ah, bkh[nt]);
                    mma_bf16(s[nt], ah, bkl[nt]);
                    mma_bf16(s[nt], al, bkh[nt]);
                }
            }

            // ---- causal mask (diagonal band only) ----
            if (kt0 + 63 > t0 + wq0) {
#pragma unroll
                for (int nt = 0; nt < 8; nt++) {
                    int col = kt0 + nt * 8 + tig * 2;
                    if (col     > row0) s[nt][0] = -1e30f;
                    if (col + 1 > row0) s[nt][1] = -1e30f;
                    if (col     > row1) s[nt][2] = -1e30f;
                    if (col + 1 > row1) s[nt][3] = -1e30f;
                }
            }

            // ---- online softmax (fp32) ----
            float mx0 = -1e30f, mx1 = -1e30f;
#pragma unroll
            for (int nt = 0; nt < 8; nt++) {
                mx0 = fmaxf(mx0, fmaxf(s[nt][0], s[nt][1]));
                mx1 = fmaxf(mx1, fmaxf(s[nt][2], s[nt][3]));
            }
#pragma unroll
            for (int off = 1; off < 4; off <<= 1) {
                mx0 = fmaxf(mx0, __shfl_xor_sync(0xFFFFFFFFu, mx0, off));
                mx1 = fmaxf(mx1, __shfl_xor_sync(0xFFFFFFFFu, mx1, off));
            }
            float nm0 = fmaxf(m0, mx0), nm1 = fmaxf(m1, mx1);
            float a0 = __expf(m0 - nm0), a1 = __expf(m1 - nm1);
            float sum0 = 0.f, sum1 = 0.f;
#pragma unroll
            for (int nt = 0; nt < 8; nt++) {
                s[nt][0] = __expf(s[nt][0] - nm0);
                s[nt][1] = __expf(s[nt][1] - nm0);
                s[nt][2] = __expf(s[nt][2] - nm1);
                s[nt][3] = __expf(s[nt][3] - nm1);
                sum0 += s[nt][0] + s[nt][1];
                sum1 += s[nt][2] + s[nt][3];
            }
#pragma unroll
            for (int off = 1; off < 4; off <<= 1) {
                sum0 += __shfl_xor_sync(0xFFFFFFFFu, sum0, off);
                sum1 += __shfl_xor_sync(0xFFFFFFFFu, sum1, off);
            }
            l0 = l0 * a0 + sum0;
            l1 = l1 * a1 + sum1;
            m0 = nm0; m1 = nm1;
#pragma unroll
            for (int nt = 0; nt < 8; nt++) {
                o[nt][0] *= a0; o[nt][1] *= a0;
                o[nt][2] *= a1; o[nt][3] *= a1;
            }

            // ---- pack P fragments (split bf16) ----
            uint32_t ph[4][4], pl[4][4];
#pragma unroll
            for (int ks = 0; ks < 4; ks++) {
                split2(s[2 * ks][0],     s[2 * ks][1],     ph[ks][0], pl[ks][0]);
                split2(s[2 * ks][2],     s[2 * ks][3],     ph[ks][1], pl[ks][1]);
                split2(s[2 * ks + 1][0], s[2 * ks + 1][1], ph[ks][2], pl[ks][2]);
                split2(s[2 * ks + 1][2], s[2 * ks + 1][3], ph[ks][3], pl[ks][3]);
            }

            // ---- O += P @ V (split 3-MMA, V via ldmatrix.trans) ----
#pragma unroll
            for (int ks = 0; ks < 4; ks++) {
                uint32_t bvh[8][2], bvl[8][2];
#pragma unroll
                for (int db = 0; db < 4; db++) {
                    uint32_t voff = (ks * 16 + lrow) * 144 + db * 32 + lcol * 2;
                    uint32_t r0, r1, r2, r3;
                    ldsm_x4_t(r0, r1, r2, r3, st + 18432 + voff);
                    bvh[db * 2][0] = r0; bvh[db * 2][1] = r1;
                    bvh[db * 2 + 1][0] = r2; bvh[db * 2 + 1][1] = r3;
                    ldsm_x4_t(r0, r1, r2, r3, st + 27648 + voff);
                    bvl[db * 2][0] = r0; bvl[db * 2][1] = r1;
                    bvl[db * 2 + 1][0] = r2; bvl[db * 2 + 1][1] = r3;
                }
#pragma unroll
                for (int nt = 0; nt < 8; nt++) {
                    mma_bf16(o[nt], ph[ks], bvh[nt]);
                    mma_bf16(o[nt], ph[ks], bvl[nt]);
                    mma_bf16(o[nt], pl[ks], bvh[nt]);
                }
            }
        }
        __syncthreads();
        if (kt + 2 < nkt) { load_kv(kt + 2); CP_COMMIT(); }
    }

    // ---- epilogue: ctx split bf16, [m = t*B + b_][h*64 + d] ----
    const float i0 = 1.f / l0;
    const float i1 = 1.f / l1;
#pragma unroll
    for (int nt = 0; nt < 8; nt++) {
        const int d = nt * 8 + tig * 2;
        size_t o0 = ((size_t)(row0 * BATCH + b_)) * D_MODEL + h * 64 + d;
        size_t o1 = ((size_t)(row1 * BATCH + b_)) * D_MODEL + h * 64 + d;
        uint32_t hi, lo;
        split2(o[nt][0] * i0, o[nt][1] * i0, hi, lo);
        *(uint32_t*)(chi + o0) = hi;
        *(uint32_t*)(clo + o0) = lo;
        split2(o[nt][2] * i1, o[nt][3] * i1, hi, lo);
        *(uint32_t*)(chi + o1) = hi;
        *(uint32_t*)(clo + o1) = lo;
    }
}

// ---------------------------------------------------------------------------
extern "C" void kernel_launch(void* const* d_in, const int* in_sizes, int n_in,
                              void* d_out, int out_size)
{
    const float* x    = (const float*)d_in[0];
    const float* Wqkv = (const float*)d_in[1];
    const float* bqkv = (const float*)d_in[2];
    const float* Wout = (const float*)d_in[3];
    const float* bout = (const float*)d_in[4];
    float* out = (float*)d_out;

    const int M = in_sizes[0] / D_MODEL;   // 4096
    const int T = M / BATCH;               // 2048
    const int nqt = T / 128;               // 16

    __nv_bfloat16 *xhi, *xlo, *w1hi, *w1lo, *w2hi, *w2lo, *chi, *clo;
    __nv_bfloat16 *qhi, *qlo, *khi, *klo, *vhi, *vlo;
    cudaGetSymbolAddress((void**)&xhi, g_xhi);
    cudaGetSymbolAddress((void**)&xlo, g_xlo);
    cudaGetSymbolAddress((void**)&w1hi, g_w1hi);
    cudaGetSymbolAddress((void**)&w1lo, g_w1lo);
    cudaGetSymbolAddress((void**)&w2hi, g_w2hi);
    cudaGetSymbolAddress((void**)&w2lo, g_w2lo);
    cudaGetSymbolAddress((void**)&chi, g_chi);
    cudaGetSymbolAddress((void**)&clo, g_clo);
    cudaGetSymbolAddress((void**)&qhi, g_qhi);
    cudaGetSymbolAddress((void**)&qlo, g_qlo);
    cudaGetSymbolAddress((void**)&khi, g_khi);
    cudaGetSymbolAddress((void**)&klo, g_klo);
    cudaGetSymbolAddress((void**)&vhi, g_vhi);
    cudaGetSymbolAddress((void**)&vlo, g_vlo);

    cudaFuncSetAttribute(gemm_mma<0>, cudaFuncAttributeMaxDynamicSharedMemorySize, GSMEM_TOTAL);
    cudaFuncSetAttribute(gemm_mma<1>, cudaFuncAttributeMaxDynamicSharedMemorySize, GSMEM_TOTAL);
    cudaFuncSetAttribute(flash_mma, cudaFuncAttributeMaxDynamicSharedMemorySize, FSMEM_TOTAL);

    // 1) split inputs
    split_convert<<<(M * D_MODEL / 4 + 255) / 256, 256>>>(x, xhi, xlo, M * D_MODEL / 4);
    split_convert_T<<<dim3(3 * D_MODEL / 32, D_MODEL / 32), dim3(32, 8)>>>(
        Wqkv, w1hi, w1lo, D_MODEL, 3 * D_MODEL);

    // 2) QKV projection -> split bf16 q/k/v in [B,H,T,64]
    gemm_mma<1><<<dim3(3 * D_MODEL / 128, M / 128), 256, GSMEM_TOTAL>>>(
        xhi, xlo, w1hi, w1lo, bqkv, nullptr,
        qhi, qlo, khi, klo, vhi, vlo, M, 3 * D_MODEL, D_MODEL);

    // 3) causal flash attention on HMMA -> split bf16 ctx
    flash_mma<<<32 * nqt, 256, FSMEM_TOTAL>>>(qhi, qlo, khi, klo, vhi, vlo, chi, clo, nqt);

    // 4) output projection
    split_convert_T<<<dim3(D_MODEL / 32, D_MODEL / 32), dim3(32, 8)>>>(
        Wout, w2hi, w2lo, D_MODEL, D_MODEL);
    gemm_mma<0><<<dim3(D_MODEL / 128, M / 128), 256, GSMEM_TOTAL>>>(
        chi, clo, w2hi, w2lo, bout, out,
        nullptr, nullptr, nullptr, nullptr, nullptr, nullptr, M, D_MODEL, D_MODEL);
}

// round 6
// speedup vs baseline: 3.0634x; 1.0047x over previous
#include <cuda_runtime.h>
#include <cuda_bf16.h>
#include <cstdint>
#include <math.h>

#define D_MODEL 1024
#define N_HEADS 16
#define HEAD_DIM 64
#define BATCH 2
#define SEQ 2048

// ---------------------------------------------------------------------------
// Scratch (allocation-free rule: __device__ globals)
// ---------------------------------------------------------------------------
__device__ __nv_bfloat16 g_xhi[4096 * 1024];        // x split
__device__ __nv_bfloat16 g_xlo[4096 * 1024];
__device__ __nv_bfloat16 g_w1hi[3072 * 1024];       // Wqkv^T split  [N,K]
__device__ __nv_bfloat16 g_w1lo[3072 * 1024];
__device__ __nv_bfloat16 g_w2hi[1024 * 1024];       // Wout^T split  [N,K]
__device__ __nv_bfloat16 g_w2lo[1024 * 1024];
// q/k/v in [B,H,T,64] split bf16 (q prescaled by 0.125)
__device__ __nv_bfloat16 g_qhi[BATCH * N_HEADS * SEQ * 64];
__device__ __nv_bfloat16 g_qlo[BATCH * N_HEADS * SEQ * 64];
__device__ __nv_bfloat16 g_khi[BATCH * N_HEADS * SEQ * 64];
__device__ __nv_bfloat16 g_klo[BATCH * N_HEADS * SEQ * 64];
__device__ __nv_bfloat16 g_vhi[BATCH * N_HEADS * SEQ * 64];
__device__ __nv_bfloat16 g_vlo[BATCH * N_HEADS * SEQ * 64];
// attention output (ctx) split bf16, [m=T*B rows][1024]
__device__ __nv_bfloat16 g_chi[4096 * 1024];
__device__ __nv_bfloat16 g_clo[4096 * 1024];

// ---------------------------------------------------------------------------
// PTX helpers (plain sm_103-compatible: mma.sync / ldmatrix / cp.async)
// ---------------------------------------------------------------------------
__device__ __forceinline__ uint32_t smem_to_u32(const void* p) {
    uint32_t a;
    asm("{ .reg .u64 t; cvta.to.shared.u64 t, %1; cvt.u32.u64 %0, t; }" : "=r"(a) : "l"(p));
    return a;
}
__device__ __forceinline__ void cp_async16(uint32_t dst, const void* src) {
    asm volatile("cp.async.cg.shared.global [%0], [%1], 16;" :: "r"(dst), "l"(src) : "memory");
}
#define CP_COMMIT() asm volatile("cp.async.commit_group;" ::: "memory")
#define CP_WAIT(n)  asm volatile("cp.async.wait_group %0;" :: "n"(n) : "memory")

__device__ __forceinline__ void ldsm_x4(uint32_t& r0, uint32_t& r1, uint32_t& r2, uint32_t& r3,
                                        uint32_t addr) {
    asm volatile("ldmatrix.sync.aligned.m8n8.x4.shared.b16 {%0,%1,%2,%3}, [%4];"
                 : "=r"(r0), "=r"(r1), "=r"(r2), "=r"(r3) : "r"(addr));
}
__device__ __forceinline__ void ldsm_x4_t(uint32_t& r0, uint32_t& r1, uint32_t& r2, uint32_t& r3,
                                          uint32_t addr) {
    asm volatile("ldmatrix.sync.aligned.m8n8.x4.trans.shared.b16 {%0,%1,%2,%3}, [%4];"
                 : "=r"(r0), "=r"(r1), "=r"(r2), "=r"(r3) : "r"(addr));
}
__device__ __forceinline__ void mma_bf16(float c[4], const uint32_t a[4], const uint32_t b[2]) {
    asm volatile(
        "mma.sync.aligned.m16n8k16.row.col.f32.bf16.bf16.f32 "
        "{%0,%1,%2,%3}, {%4,%5,%6,%7}, {%8,%9}, {%0,%1,%2,%3};"
        : "+f"(c[0]), "+f"(c[1]), "+f"(c[2]), "+f"(c[3])
        : "r"(a[0]), "r"(a[1]), "r"(a[2]), "r"(a[3]), "r"(b[0]), "r"(b[1]));
}

__device__ __forceinline__ void split2(float x, float y, uint32_t& hi, uint32_t& lo) {
    __nv_bfloat16 hx = __float2bfloat16(x), hy = __float2bfloat16(y);
    __nv_bfloat162 h2 = __halves2bfloat162(hx, hy);
    __nv_bfloat162 l2 = __halves2bfloat162(
        __float2bfloat16(x - __bfloat162float(hx)),
        __float2bfloat16(y - __bfloat162float(hy)));
    hi = *(uint32_t*)&h2;
    lo = *(uint32_t*)&l2;
}

// ---------------------------------------------------------------------------
// Split-precision conversion kernels
// ---------------------------------------------------------------------------
__global__ __launch_bounds__(256) void split_convert(
    const float* __restrict__ in, __nv_bfloat16* __restrict__ hi,
    __nv_bfloat16* __restrict__ lo, int n4)
{
    int i = blockIdx.x * blockDim.x + threadIdx.x;
    if (i >= n4) return;
    float4 v = ((const float4*)in)[i];
    __nv_bfloat16 h0 = __float2bfloat16(v.x);
    __nv_bfloat16 h1 = __float2bfloat16(v.y);
    __nv_bfloat16 h2 = __float2bfloat16(v.z);
    __nv_bfloat16 h3 = __float2bfloat16(v.w);
    __nv_bfloat16 l0 = __float2bfloat16(v.x - __bfloat162float(h0));
    __nv_bfloat16 l1 = __float2bfloat16(v.y - __bfloat162float(h1));
    __nv_bfloat16 l2 = __float2bfloat16(v.z - __bfloat162float(h2));
    __nv_bfloat16 l3 = __float2bfloat16(v.w - __bfloat162float(h3));
    ((__nv_bfloat162*)hi)[i * 2]     = __halves2bfloat162(h0, h1);
    ((__nv_bfloat162*)hi)[i * 2 + 1] = __halves2bfloat162(h2, h3);
    ((__nv_bfloat162*)lo)[i * 2]     = __halves2bfloat162(l0, l1);
    ((__nv_bfloat162*)lo)[i * 2 + 1] = __halves2bfloat162(l2, l3);
}

// W[K,N] fp32 -> Wt_hi/Wt_lo [N,K] bf16 (transpose + split). 32x32 tiles.
__global__ __launch_bounds__(256) void split_convert_T(
    const float* __restrict__ W, __nv_bfloat16* __restrict__ hi,
    __nv_bfloat16* __restrict__ lo, int K, int N)
{
    __shared__ float t[32][33];
    const int n0 = blockIdx.x * 32;
    const int k0 = blockIdx.y * 32;
#pragma unroll
    for (int i = 0; i < 4; i++) {
        int k = k0 + threadIdx.y + i * 8;
        t[threadIdx.y + i * 8][threadIdx.x] = W[(size_t)k * N + n0 + threadIdx.x];
    }
    __syncthreads();
#pragma unroll
    for (int i = 0; i < 4; i++) {
        int nn = n0 + threadIdx.y + i * 8;
        float v = t[threadIdx.x][threadIdx.y + i * 8];
        __nv_bfloat16 h = __float2bfloat16(v);
        float r = v - __bfloat162float(h);
        hi[(size_t)nn * K + k0 + threadIdx.x] = h;
        lo[(size_t)nn * K + k0 + threadIdx.x] = __float2bfloat16(r);
    }
}

// ---------------------------------------------------------------------------
// HMMA bf16-split GEMM: C = A[M,K] @ Bt[N,K]^T + bias
// 2-stage cp.async pipeline, 2 CTAs/SM.
// MODE 0: write fp32 C. MODE 1: QKV epilogue -> split bf16 q/k/v [B,H,T,64].
// ---------------------------------------------------------------------------
#define BK 32
#define ASTRIDE 40                     // bf16 elems per smem row (32 + 8 pad)
#define TILE_BYTES (128 * ASTRIDE * 2) // 10240
#define T_AHI 0
#define T_ALO (1 * TILE_BYTES)
#define T_BHI (2 * TILE_BYTES)
#define T_BLO (3 * TILE_BYTES)
#define STAGE_BYTES (4 * TILE_BYTES)   // 40960
#define GSMEM_TOTAL (2 * STAGE_BYTES)  // 81920

template <int MODE>
__global__ __launch_bounds__(256, 2) void gemm_mma(
    const __nv_bfloat16* __restrict__ Ahi, const __nv_bfloat16* __restrict__ Alo,
    const __nv_bfloat16* __restrict__ Bhi, const __nv_bfloat16* __restrict__ Blo,
    const float* __restrict__ bias, float* __restrict__ C,
    __nv_bfloat16* __restrict__ qhi, __nv_bfloat16* __restrict__ qlo,
    __nv_bfloat16* __restrict__ khi, __nv_bfloat16* __restrict__ klo,
    __nv_bfloat16* __restrict__ vhi, __nv_bfloat16* __restrict__ vlo,
    int M, int N, int K)
{
    extern __shared__ char smem[];
    const uint32_t smem_base = smem_to_u32(smem);
    const int tid  = threadIdx.x;
    const int wid  = tid >> 5;
    const int lane = tid & 31;
    const int bm = blockIdx.y * 128;
    const int bn = blockIdx.x * 128;
    const int wm = (wid & 3) * 32;
    const int wn = (wid >> 2) * 64;

    const __nv_bfloat16* srcs[4]  = {Ahi, Alo, Bhi, Blo};
    const int rows0[4]            = {bm, bm, bn, bn};

    auto load_stage = [&](int it) {
        const uint32_t sb = smem_base + (it & 1) * STAGE_BYTES;
        const int k0 = it * BK;
#pragma unroll
        for (int c = tid; c < 2048; c += 256) {
            int mat = c >> 9;
            int r   = (c >> 2) & 127;
            int kc  = (c & 3) * 8;
            const __nv_bfloat16* src = srcs[mat] + (size_t)(rows0[mat] + r) * K + k0 + kc;
            uint32_t dst = sb + mat * TILE_BYTES + (r * ASTRIDE + kc) * 2;
            cp_async16(dst, src);
        }
    };

    const int NK = K / BK;
    load_stage(0); CP_COMMIT();

    float acc[2][8][4];
#pragma unroll
    for (int mt = 0; mt < 2; mt++)
#pragma unroll
        for (int nt = 0; nt < 8; nt++)
#pragma unroll
            for (int i = 0; i < 4; i++) acc[mt][nt][i] = 0.f;

    const int lrow = lane & 15;
    const int lcol = (lane >> 4) * 8;

    for (int kt = 0; kt < NK; kt++) {
        if (kt + 1 < NK) { load_stage(kt + 1); CP_COMMIT(); CP_WAIT(1); }
        else             { CP_WAIT(0); }
        __syncthreads();
        const uint32_t sb = smem_base + (kt & 1) * STAGE_BYTES;

#pragma unroll
        for (int ks = 0; ks < 2; ks++) {
            uint32_t ah[2][4], al[2][4];
#pragma unroll
            for (int mt = 0; mt < 2; mt++) {
                uint32_t off = ((wm + mt * 16 + lrow) * ASTRIDE + ks * 16 + lcol) * 2;
                ldsm_x4(ah[mt][0], ah[mt][1], ah[mt][2], ah[mt][3], sb + T_AHI + off);
                ldsm_x4(al[mt][0], al[mt][1], al[mt][2], al[mt][3], sb + T_ALO + off);
            }
            uint32_t bh[8][2], bl[8][2];
#pragma unroll
            for (int np = 0; np < 4; np++) {
                uint32_t off = ((wn + np * 16 + lrow) * ASTRIDE + ks * 16 + lcol) * 2;
                uint32_t r0, r1, r2, r3;
                ldsm_x4(r0, r1, r2, r3, sb + T_BHI + off);
                bh[np * 2][0] = r0; bh[np * 2][1] = r2;
                bh[np * 2 + 1][0] = r1; bh[np * 2 + 1][1] = r3;
                ldsm_x4(r0, r1, r2, r3, sb + T_BLO + off);
                bl[np * 2][0] = r0; bl[np * 2][1] = r2;
                bl[np * 2 + 1][0] = r1; bl[np * 2 + 1][1] = r3;
            }
#pragma unroll
            for (int mt = 0; mt < 2; mt++)
#pragma unroll
                for (int nt = 0; nt < 8; nt++) {
                    mma_bf16(acc[mt][nt], ah[mt], bh[nt]);
                    mma_bf16(acc[mt][nt], ah[mt], bl[nt]);
                    mma_bf16(acc[mt][nt], al[mt], bh[nt]);
                }
        }
        __syncthreads();
    }

    const int trow = lane >> 2;
    const int tcol = (lane & 3) * 2;

    if (MODE == 0) {
#pragma unroll
        for (int mt = 0; mt < 2; mt++) {
            const int grow = bm + wm + mt * 16 + trow;
#pragma unroll
            for (int nt = 0; nt < 8; nt++) {
                const int gcol = bn + wn + nt * 8 + tcol;
                float b0 = bias[gcol], b1 = bias[gcol + 1];
                float2 o0 = {acc[mt][nt][0] + b0, acc[mt][nt][1] + b1};
                float2 o1 = {acc[mt][nt][2] + b0, acc[mt][nt][3] + b1};
                *(float2*)(C + (size_t)grow * N + gcol)       = o0;
                *(float2*)(C + (size_t)(grow + 8) * N + gcol) = o1;
            }
        }
    } else {
        const int sec = bn >> 10;
        __nv_bfloat16* dhi = (sec == 0) ? qhi : (sec == 1) ? khi : vhi;
        __nv_bfloat16* dlo = (sec == 0) ? qlo : (sec == 1) ? klo : vlo;
        const float scl = (sec == 0) ? 0.125f : 1.f;
#pragma unroll
        for (int mt = 0; mt < 2; mt++) {
            const int grow = bm + wm + mt * 16 + trow;
#pragma unroll
            for (int nt = 0; nt < 8; nt++) {
                const int gcol = bn + wn + nt * 8 + tcol;
                const int hh = (gcol >> 6) & 15;
                const int dd = gcol & 63;
                float b0 = bias[gcol], b1 = bias[gcol + 1];
#pragma unroll
                for (int rr = 0; rr < 2; rr++) {
                    int row = grow + rr * 8;
                    int t = row >> 1, b_ = row & 1;
                    size_t idx = (((size_t)(b_ * 16 + hh)) * SEQ + t) * 64 + dd;
                    float v0 = (acc[mt][nt][rr * 2]     + b0) * scl;
                    float v1 = (acc[mt][nt][rr * 2 + 1] + b1) * scl;
                    uint32_t hi, lo;
                    split2(v0, v1, hi, lo);
                    *(uint32_t*)(dhi + idx) = hi;
                    *(uint32_t*)(dlo + idx) = lo;
                }
            }
        }
    }
}

// ---------------------------------------------------------------------------
// Flash attention on HMMA, split-bf16, fp32 softmax. 1 CTA/SM, 3-stage KV
// ring -> ONE __syncthreads per k-tile (stage kt+2 never aliases stage kt).
// CTA: 128 queries x one (b,h). 8 warps x 16 rows. 64-key tiles.
// ---------------------------------------------------------------------------
#define FQ_HI 0
#define FQ_LO 18432
#define FKV_O 36864
#define FKV_STAGE 36864                // khi 0 | klo 9216 | vhi 18432 | vlo 27648
#define FSMEM_TOTAL (FKV_O + 3 * FKV_STAGE)  // 147456

__global__ __launch_bounds__(256) void flash_mma(
    const __nv_bfloat16* __restrict__ qhi, const __nv_bfloat16* __restrict__ qlo,
    const __nv_bfloat16* __restrict__ khi, const __nv_bfloat16* __restrict__ klo,
    const __nv_bfloat16* __restrict__ vhi, const __nv_bfloat16* __restrict__ vlo,
    __nv_bfloat16* __restrict__ chi, __nv_bfloat16* __restrict__ clo,
    int nqt)
{
    extern __shared__ char smem[];
    const uint32_t sb = smem_to_u32(smem);
    const int tid  = threadIdx.x;
    const int wid  = tid >> 5;
    const int lane = tid & 31;

    const int bx = blockIdx.x;
    const int bh = bx & 31;                 // b*16 + h
    const int qt = nqt - 1 - (bx >> 5);     // big tiles first
    const int b_ = bh >> 4;
    const int h  = bh & 15;
    const int t0 = qt * 128;
    const int nkt = 2 * (qt + 1);
    const size_t hb = ((size_t)(b_ * 16 + h)) * SEQ * 64;

#pragma unroll
    for (int c = tid; c < 2048; c += 256) {
        int tile = c >> 10, r = (c >> 3) & 127, ck = c & 7;
        const __nv_bfloat16* src = (tile ? qlo : qhi) + hb + (size_t)(t0 + r) * 64 + ck * 8;
        cp_async16(sb + (tile ? FQ_LO : FQ_HI) + r * 144 + ck * 16, src);
    }
    const __nv_bfloat16* kvsrc[4] = {khi, klo, vhi, vlo};
    auto kv_stage = [&](int kt) -> uint32_t {
        return sb + FKV_O + (kt % 3) * FKV_STAGE;
    };
    auto load_kv = [&](int kt) {
        uint32_t st = kv_stage(kt);
        int kt0 = kt * 64;
#pragma unroll
        for (int c = tid; c < 2048; c += 256) {
            int tile = c >> 9, r = (c >> 3) & 63, ck = c & 7;
            cp_async16(st + tile * 9216 + r * 144 + ck * 16,
                       kvsrc[tile] + hb + (size_t)(kt0 + r) * 64 + ck * 8);
        }
    };
    load_kv(0); CP_COMMIT();
    if (nkt > 1) { load_kv(1); CP_COMMIT(); }

    float o[8][4];
#pragma unroll
    for (int nt = 0; nt < 8; nt++)
#pragma unroll
        for (int i = 0; i < 4; i++) o[nt][i] = 0.f;
    float m0 = -1e30f, m1 = -1e30f, l0 = 0.f, l1 = 0.f;

    const int lrow = lane & 15;
    const int lcol = (lane >> 4) * 8;
    const int g    = lane >> 2;
    const int tig  = lane & 3;
    const int wq0  = wid * 16;
    const int row0 = t0 + wq0 + g;
    const int row1 = row0 + 8;

    for (int kt = 0; kt < nkt; kt++) {
        if (kt + 1 < nkt) { CP_WAIT(1); } else { CP_WAIT(0); }
        __syncthreads();          // the ONLY barrier per k-tile
        const int kt0 = kt * 64;
        const uint32_t st = kv_stage(kt);

        if (kt0 <= t0 + wq0 + 15) {
            // ---- S = Q @ K^T (split 3-MMA) ----
            float s[8][4];
#pragma unroll
            for (int nt = 0; nt < 8; nt++)
#pragma unroll
                for (int i = 0; i < 4; i++) s[nt][i] = 0.f;

#pragma unroll
            for (int ks = 0; ks < 4; ks++) {
                uint32_t ah[4], al[4];
                uint32_t qoff = (wq0 + lrow) * 144 + ks * 32 + lcol * 2;
                ldsm_x4(ah[0], ah[1], ah[2], ah[3], sb + FQ_HI + qoff);
                ldsm_x4(al[0], al[1], al[2], al[3], sb + FQ_LO + qoff);
                uint32_t bkh[8][2], bkl[8][2];
#pragma unroll
                for (int np = 0; np < 4; np++) {
                    uint32_t koff = (np * 16 + lrow) * 144 + ks * 32 + lcol * 2;
                    uint32_t r0, r1, r2, r3;
                    ldsm_x4(r0, r1, r2, r3, st + koff);
                    bkh[np * 2][0] = r0; bkh[np * 2][1] = r2;
                    bkh[np * 2 + 1][0] = r1; bkh[np * 2 + 1][1] = r3;
                    ldsm_x4(r0, r1, r2, r3, st + 9216 + koff);
                    bkl[np * 2][0] = r0; bkl[np * 2][1] = r2;
                    bkl[np * 2 + 1][0] = r1; bkl[np * 2 + 1][1] = r3;
                }
#pragma unroll
                for (int nt = 0; nt < 8; nt++) {
                    mma_bf16(s[nt], ah, bkh[nt]);
                    mma_bf16(s[nt], ah, bkl[nt]);
                    mma_bf16(s[nt], al, bkh[nt]);
                }
            }

            // ---- causal mask (diagonal band only) ----
            if (kt0 + 63 > t0 + wq0) {
#pragma unroll
                for (int nt = 0; nt < 8; nt++) {
                    int col = kt0 + nt * 8 + tig * 2;
                    if (col     > row0) s[nt][0] = -1e30f;
                    if (col + 1 > row0) s[nt][1] = -1e30f;
                    if (col     > row1) s[nt][2] = -1e30f;
                    if (col + 1 > row1) s[nt][3] = -1e30f;
                }
            }

            // ---- online softmax (fp32) ----
            float mx0 = -1e30f, mx1 = -1e30f;
#pragma unroll
            for (int nt = 0; nt < 8; nt++) {
                mx0 = fmaxf(mx0, fmaxf(s[nt][0], s[nt][1]));
                mx1 = fmaxf(mx1, fmaxf(s[nt][2], s[nt][3]));
            }
#pragma unroll
            for (int off = 1; off < 4; off <<= 1) {
                mx0 = fmaxf(mx0, __shfl_xor_sync(0xFFFFFFFFu, mx0, off));
                mx1 = fmaxf(mx1, __shfl_xor_sync(0xFFFFFFFFu, mx1, off));
            }
            float nm0 = fmaxf(m0, mx0), nm1 = fmaxf(m1, mx1);
            float a0 = __expf(m0 - nm0), a1 = __expf(m1 - nm1);
            float sum0 = 0.f, sum1 = 0.f;
#pragma unroll
            for (int nt = 0; nt < 8; nt++) {
                s[nt][0] = __expf(s[nt][0] - nm0);
                s[nt][1] = __expf(s[nt][1] - nm0);
                s[nt][2] = __expf(s[nt][2] - nm1);
                s[nt][3] = __expf(s[nt][3] - nm1);
                sum0 += s[nt][0] + s[nt][1];
                sum1 += s[nt][2] + s[nt][3];
            }
#pragma unroll
            for (int off = 1; off < 4; off <<= 1) {
                sum0 += __shfl_xor_sync(0xFFFFFFFFu, sum0, off);
                sum1 += __shfl_xor_sync(0xFFFFFFFFu, sum1, off);
            }
            l0 = l0 * a0 + sum0;
            l1 = l1 * a1 + sum1;
            m0 = nm0; m1 = nm1;
#pragma unroll
            for (int nt = 0; nt < 8; nt++) {
                o[nt][0] *= a0; o[nt][1] *= a0;
                o[nt][2] *= a1; o[nt][3] *= a1;
            }

            // ---- pack P fragments (split bf16) ----
            uint32_t ph[4][4], pl[4][4];
#pragma unroll
            for (int ks = 0; ks < 4; ks++) {
                split2(s[2 * ks][0],     s[2 * ks][1],     ph[ks][0], pl[ks][0]);
                split2(s[2 * ks][2],     s[2 * ks][3],     ph[ks][1], pl[ks][1]);
                split2(s[2 * ks + 1][0], s[2 * ks + 1][1], ph[ks][2], pl[ks][2]);
                split2(s[2 * ks + 1][2], s[2 * ks + 1][3], ph[ks][3], pl[ks][3]);
            }

            // ---- O += P @ V (split 3-MMA, V via ldmatrix.trans) ----
#pragma unroll
            for (int ks = 0; ks < 4; ks++) {
                uint32_t bvh[8][2], bvl[8][2];
#pragma unroll
                for (int db = 0; db < 4; db++) {
                    uint32_t voff = (ks * 16 + lrow) * 144 + db * 32 + lcol * 2;
                    uint32_t r0, r1, r2, r3;
                    ldsm_x4_t(r0, r1, r2, r3, st + 18432 + voff);
                    bvh[db * 2][0] = r0; bvh[db * 2][1] = r1;
                    bvh[db * 2 + 1][0] = r2; bvh[db * 2 + 1][1] = r3;
                    ldsm_x4_t(r0, r1, r2, r3, st + 27648 + voff);
                    bvl[db * 2][0] = r0; bvl[db * 2][1] = r1;
                    bvl[db * 2 + 1][0] = r2; bvl[db * 2 + 1][1] = r3;
                }
#pragma unroll
                for (int nt = 0; nt < 8; nt++) {
                    mma_bf16(o[nt], ph[ks], bvh[nt]);
                    mma_bf16(o[nt], ph[ks], bvl[nt]);
                    mma_bf16(o[nt], pl[ks], bvh[nt]);
                }
            }
        }
        if (kt + 2 < nkt) { load_kv(kt + 2); CP_COMMIT(); }
    }

    // ---- epilogue: ctx split bf16, [m = t*B + b_][h*64 + d] ----
    const float i0 = 1.f / l0;
    const float i1 = 1.f / l1;
#pragma unroll
    for (int nt = 0; nt < 8; nt++) {
        const int d = nt * 8 + tig * 2;
        size_t o0 = ((size_t)(row0 * BATCH + b_)) * D_MODEL + h * 64 + d;
        size_t o1 = ((size_t)(row1 * BATCH + b_)) * D_MODEL + h * 64 + d;
        uint32_t hi, lo;
        split2(o[nt][0] * i0, o[nt][1] * i0, hi, lo);
        *(uint32_t*)(chi + o0) = hi;
        *(uint32_t*)(clo + o0) = lo;
        split2(o[nt][2] * i1, o[nt][3] * i1, hi, lo);
        *(uint32_t*)(chi + o1) = hi;
        *(uint32_t*)(clo + o1) = lo;
    }
}

// ---------------------------------------------------------------------------
extern "C" void kernel_launch(void* const* d_in, const int* in_sizes, int n_in,
                              void* d_out, int out_size)
{
    const float* x    = (const float*)d_in[0];
    const float* Wqkv = (const float*)d_in[1];
    const float* bqkv = (const float*)d_in[2];
    const float* Wout = (const float*)d_in[3];
    const float* bout = (const float*)d_in[4];
    float* out = (float*)d_out;

    const int M = in_sizes[0] / D_MODEL;   // 4096
    const int T = M / BATCH;               // 2048
    const int nqt = T / 128;               // 16

    __nv_bfloat16 *xhi, *xlo, *w1hi, *w1lo, *w2hi, *w2lo, *chi, *clo;
    __nv_bfloat16 *qhi, *qlo, *khi, *klo, *vhi, *vlo;
    cudaGetSymbolAddress((void**)&xhi, g_xhi);
    cudaGetSymbolAddress((void**)&xlo, g_xlo);
    cudaGetSymbolAddress((void**)&w1hi, g_w1hi);
    cudaGetSymbolAddress((void**)&w1lo, g_w1lo);
    cudaGetSymbolAddress((void**)&w2hi, g_w2hi);
    cudaGetSymbolAddress((void**)&w2lo, g_w2lo);
    cudaGetSymbolAddress((void**)&chi, g_chi);
    cudaGetSymbolAddress((void**)&clo, g_clo);
    cudaGetSymbolAddress((void**)&qhi, g_qhi);
    cudaGetSymbolAddress((void**)&qlo, g_qlo);
    cudaGetSymbolAddress((void**)&khi, g_khi);
    cudaGetSymbolAddress((void**)&klo, g_klo);
    cudaGetSymbolAddress((void**)&vhi, g_vhi);
    cudaGetSymbolAddress((void**)&vlo, g_vlo);

    cudaFuncSetAttribute(gemm_mma<0>, cudaFuncAttributeMaxDynamicSharedMemorySize, GSMEM_TOTAL);
    cudaFuncSetAttribute(gemm_mma<1>, cudaFuncAttributeMaxDynamicSharedMemorySize, GSMEM_TOTAL);
    cudaFuncSetAttribute(flash_mma, cudaFuncAttributeMaxDynamicSharedMemorySize, FSMEM_TOTAL);

    // 1) split inputs
    split_convert<<<(M * D_MODEL / 4 + 255) / 256, 256>>>(x, xhi, xlo, M * D_MODEL / 4);
    split_convert_T<<<dim3(3 * D_MODEL / 32, D_MODEL / 32), dim3(32, 8)>>>(
        Wqkv, w1hi, w1lo, D_MODEL, 3 * D_MODEL);

    // 2) QKV projection -> split bf16 q/k/v in [B,H,T,64]
    gemm_mma<1><<<dim3(3 * D_MODEL / 128, M / 128), 256, GSMEM_TOTAL>>>(
        xhi, xlo, w1hi, w1lo, bqkv, nullptr,
        qhi, qlo, khi, klo, vhi, vlo, M, 3 * D_MODEL, D_MODEL);

    // 3) causal flash attention on HMMA -> split bf16 ctx
    flash_mma<<<32 * nqt, 256, FSMEM_TOTAL>>>(qhi, qlo, khi, klo, vhi, vlo, chi, clo, nqt);

    // 4) output projection
    split_convert_T<<<dim3(D_MODEL / 32, D_MODEL / 32), dim3(32, 8)>>>(
        Wout, w2hi, w2lo, D_MODEL, D_MODEL);
    gemm_mma<0><<<dim3(D_MODEL / 128, M / 128), 256, GSMEM_TOTAL>>>(
        chi, clo, w2hi, w2lo, bout, out,
        nullptr, nullptr, nullptr, nullptr, nullptr, nullptr, M, D_MODEL, D_MODEL);
}

// round 7
// speedup vs baseline: 4.5106x; 1.4724x over previous
#include <cuda_runtime.h>
#include <cuda_fp16.h>
#include <cstdint>
#include <math.h>

#define D_MODEL 1024
#define N_HEADS 16
#define HEAD_DIM 64
#define BATCH 2
#define SEQ 2048

// ---------------------------------------------------------------------------
// Scratch (allocation-free rule: __device__ globals)
// ---------------------------------------------------------------------------
__device__ __half g_xhi[4096 * 1024];        // x split (fp16 hi/lo)
__device__ __half g_xlo[4096 * 1024];
__device__ __half g_w1h[3072 * 1024];        // Wqkv^T fp16  [N,K]
__device__ __half g_w2h[1024 * 1024];        // Wout^T fp16  [N,K]
// q split, k/v single fp16, [B,H,T,64] (q prescaled by 0.125)
__device__ __half g_qhi[BATCH * N_HEADS * SEQ * 64];
__device__ __half g_qlo[BATCH * N_HEADS * SEQ * 64];
__device__ __half g_kh[BATCH * N_HEADS * SEQ * 64];
__device__ __half g_vh[BATCH * N_HEADS * SEQ * 64];
// attention output (ctx) split fp16, [m=T*B rows][1024]
__device__ __half g_chi[4096 * 1024];
__device__ __half g_clo[4096 * 1024];

// ---------------------------------------------------------------------------
// PTX helpers (plain sm_103-compatible: mma.sync / ldmatrix / cp.async)
// ---------------------------------------------------------------------------
__device__ __forceinline__ uint32_t smem_to_u32(const void* p) {
    uint32_t a;
    asm("{ .reg .u64 t; cvta.to.shared.u64 t, %1; cvt.u32.u64 %0, t; }" : "=r"(a) : "l"(p));
    return a;
}
__device__ __forceinline__ void cp_async16(uint32_t dst, const void* src) {
    asm volatile("cp.async.cg.shared.global [%0], [%1], 16;" :: "r"(dst), "l"(src) : "memory");
}
#define CP_COMMIT() asm volatile("cp.async.commit_group;" ::: "memory")
#define CP_WAIT(n)  asm volatile("cp.async.wait_group %0;" :: "n"(n) : "memory")

__device__ __forceinline__ void ldsm_x4(uint32_t& r0, uint32_t& r1, uint32_t& r2, uint32_t& r3,
                                        uint32_t addr) {
    asm volatile("ldmatrix.sync.aligned.m8n8.x4.shared.b16 {%0,%1,%2,%3}, [%4];"
                 : "=r"(r0), "=r"(r1), "=r"(r2), "=r"(r3) : "r"(addr));
}
__device__ __forceinline__ void ldsm_x4_t(uint32_t& r0, uint32_t& r1, uint32_t& r2, uint32_t& r3,
                                          uint32_t addr) {
    asm volatile("ldmatrix.sync.aligned.m8n8.x4.trans.shared.b16 {%0,%1,%2,%3}, [%4];"
                 : "=r"(r0), "=r"(r1), "=r"(r2), "=r"(r3) : "r"(addr));
}
__device__ __forceinline__ void mma_f16(float c[4], const uint32_t a[4], const uint32_t b[2]) {
    asm volatile(
        "mma.sync.aligned.m16n8k16.row.col.f32.f16.f16.f32 "
        "{%0,%1,%2,%3}, {%4,%5,%6,%7}, {%8,%9}, {%0,%1,%2,%3};"
        : "+f"(c[0]), "+f"(c[1]), "+f"(c[2]), "+f"(c[3])
        : "r"(a[0]), "r"(a[1]), "r"(a[2]), "r"(a[3]), "r"(b[0]), "r"(b[1]));
}

__device__ __forceinline__ void split2h(float x, float y, uint32_t& hi, uint32_t& lo) {
    __half hx = __float2half(x), hy = __float2half(y);
    __half2 h2 = __halves2half2(hx, hy);
    __half2 l2 = __halves2half2(
        __float2half(x - __half2float(hx)),
        __float2half(y - __half2float(hy)));
    hi = *(uint32_t*)&h2;
    lo = *(uint32_t*)&l2;
}
__device__ __forceinline__ uint32_t pack2h(float x, float y) {
    __half2 h2 = __halves2half2(__float2half(x), __float2half(y));
    return *(uint32_t*)&h2;
}

// ---------------------------------------------------------------------------
// Conversion kernels
// ---------------------------------------------------------------------------
__global__ __launch_bounds__(256) void split_convert(
    const float* __restrict__ in, __half* __restrict__ hi,
    __half* __restrict__ lo, int n4)
{
    int i = blockIdx.x * blockDim.x + threadIdx.x;
    if (i >= n4) return;
    float4 v = ((const float4*)in)[i];
    __half h0 = __float2half(v.x), h1 = __float2half(v.y);
    __half h2 = __float2half(v.z), h3 = __float2half(v.w);
    __half l0 = __float2half(v.x - __half2float(h0));
    __half l1 = __float2half(v.y - __half2float(h1));
    __half l2 = __float2half(v.z - __half2float(h2));
    __half l3 = __float2half(v.w - __half2float(h3));
    ((__half2*)hi)[i * 2]     = __halves2half2(h0, h1);
    ((__half2*)hi)[i * 2 + 1] = __halves2half2(h2, h3);
    ((__half2*)lo)[i * 2]     = __halves2half2(l0, l1);
    ((__half2*)lo)[i * 2 + 1] = __halves2half2(l2, l3);
}

// W[K,N] fp32 -> Wt [N,K] fp16 (transpose, round-to-nearest). 32x32 tiles.
__global__ __launch_bounds__(256) void convert_T(
    const float* __restrict__ W, __half* __restrict__ hi, int K, int N)
{
    __shared__ float t[32][33];
    const int n0 = blockIdx.x * 32;
    const int k0 = blockIdx.y * 32;
#pragma unroll
    for (int i = 0; i < 4; i++) {
        int k = k0 + threadIdx.y + i * 8;
        t[threadIdx.y + i * 8][threadIdx.x] = W[(size_t)k * N + n0 + threadIdx.x];
    }
    __syncthreads();
#pragma unroll
    for (int i = 0; i < 4; i++) {
        int nn = n0 + threadIdx.y + i * 8;
        hi[(size_t)nn * K + k0 + threadIdx.x] = __float2half(t[threadIdx.x][threadIdx.y + i * 8]);
    }
}

// ---------------------------------------------------------------------------
// fp16 2-MMA split GEMM: C = (Ahi+Alo)[M,K] @ Bh[N,K]^T + bias
// 3-stage cp.async ring (one barrier per kt), 2 CTAs/SM.
// MODE 0: fp32 C. MODE 1: QKV epilogue -> q split fp16 + k/v fp16 [B,H,T,64].
// ---------------------------------------------------------------------------
#define BK 32
#define ASTRIDE 40                     // fp16 elems per smem row (32 + 8 pad)
#define TILE_BYTES (128 * ASTRIDE * 2) // 10240
#define T_AHI 0
#define T_ALO (1 * TILE_BYTES)
#define T_BH  (2 * TILE_BYTES)
#define STAGE_BYTES (3 * TILE_BYTES)   // 30720
#define GSMEM_TOTAL (3 * STAGE_BYTES)  // 92160

template <int MODE>
__global__ __launch_bounds__(256, 2) void gemm_mma(
    const __half* __restrict__ Ahi, const __half* __restrict__ Alo,
    const __half* __restrict__ Bh,
    const float* __restrict__ bias, float* __restrict__ C,
    __half* __restrict__ qhi, __half* __restrict__ qlo,
    __half* __restrict__ kh, __half* __restrict__ vh,
    int M, int N, int K)
{
    extern __shared__ char smem[];
    const uint32_t smem_base = smem_to_u32(smem);
    const int tid  = threadIdx.x;
    const int wid  = tid >> 5;
    const int lane = tid & 31;
    const int bm = blockIdx.y * 128;
    const int bn = blockIdx.x * 128;
    const int wm = (wid & 3) * 32;
    const int wn = (wid >> 2) * 64;

    const __half* srcs[3] = {Ahi, Alo, Bh};
    const int rows0[3]    = {bm, bm, bn};

    auto load_stage = [&](int it) {
        const uint32_t sb = smem_base + (it % 3) * STAGE_BYTES;
        const int k0 = it * BK;
#pragma unroll
        for (int c = tid; c < 1536; c += 256) {
            int mat = c >> 9;
            int r   = (c >> 2) & 127;
            int kc  = (c & 3) * 8;
            const __half* src = srcs[mat] + (size_t)(rows0[mat] + r) * K + k0 + kc;
            uint32_t dst = sb + mat * TILE_BYTES + (r * ASTRIDE + kc) * 2;
            cp_async16(dst, src);
        }
    };

    const int NK = K / BK;
    load_stage(0); CP_COMMIT();
    load_stage(1); CP_COMMIT();

    float acc[2][8][4];
#pragma unroll
    for (int mt = 0; mt < 2; mt++)
#pragma unroll
        for (int nt = 0; nt < 8; nt++)
#pragma unroll
            for (int i = 0; i < 4; i++) acc[mt][nt][i] = 0.f;

    const int lrow = lane & 15;
    const int lcol = (lane >> 4) * 8;

    for (int kt = 0; kt < NK; kt++) {
        if (kt + 1 < NK) { CP_WAIT(1); } else { CP_WAIT(0); }
        __syncthreads();       // single barrier per kt (3-stage ring)
        const uint32_t sb = smem_base + (kt % 3) * STAGE_BYTES;

#pragma unroll
        for (int ks = 0; ks < 2; ks++) {
            uint32_t ah[2][4], al[2][4];
#pragma unroll
            for (int mt = 0; mt < 2; mt++) {
                uint32_t off = ((wm + mt * 16 + lrow) * ASTRIDE + ks * 16 + lcol) * 2;
                ldsm_x4(ah[mt][0], ah[mt][1], ah[mt][2], ah[mt][3], sb + T_AHI + off);
                ldsm_x4(al[mt][0], al[mt][1], al[mt][2], al[mt][3], sb + T_ALO + off);
            }
            uint32_t bh[8][2];
#pragma unroll
            for (int np = 0; np < 4; np++) {
                uint32_t off = ((wn + np * 16 + lrow) * ASTRIDE + ks * 16 + lcol) * 2;
                uint32_t r0, r1, r2, r3;
                ldsm_x4(r0, r1, r2, r3, sb + T_BH + off);
                bh[np * 2][0] = r0; bh[np * 2][1] = r2;
                bh[np * 2 + 1][0] = r1; bh[np * 2 + 1][1] = r3;
            }
#pragma unroll
            for (int mt = 0; mt < 2; mt++)
#pragma unroll
                for (int nt = 0; nt < 8; nt++) {
                    mma_f16(acc[mt][nt], ah[mt], bh[nt]);
                    mma_f16(acc[mt][nt], al[mt], bh[nt]);
                }
        }
        if (kt + 2 < NK) { load_stage(kt + 2); CP_COMMIT(); }
    }

    const int trow = lane >> 2;
    const int tcol = (lane & 3) * 2;

    if (MODE == 0) {
#pragma unroll
        for (int mt = 0; mt < 2; mt++) {
            const int grow = bm + wm + mt * 16 + trow;
#pragma unroll
            for (int nt = 0; nt < 8; nt++) {
                const int gcol = bn + wn + nt * 8 + tcol;
                float b0 = bias[gcol], b1 = bias[gcol + 1];
                float2 o0 = {acc[mt][nt][0] + b0, acc[mt][nt][1] + b1};
                float2 o1 = {acc[mt][nt][2] + b0, acc[mt][nt][3] + b1};
                *(float2*)(C + (size_t)grow * N + gcol)       = o0;
                *(float2*)(C + (size_t)(grow + 8) * N + gcol) = o1;
            }
        }
    } else {
        const int sec = bn >> 10;   // 0:q 1:k 2:v (uniform per CTA)
        __half* dhi = (sec == 0) ? qhi : (sec == 1) ? kh : vh;
        const float scl = (sec == 0) ? 0.125f : 1.f;
#pragma unroll
        for (int mt = 0; mt < 2; mt++) {
            const int grow = bm + wm + mt * 16 + trow;
#pragma unroll
            for (int nt = 0; nt < 8; nt++) {
                const int gcol = bn + wn + nt * 8 + tcol;
                const int hh = (gcol >> 6) & 15;
                const int dd = gcol & 63;
                float b0 = bias[gcol], b1 = bias[gcol + 1];
#pragma unroll
                for (int rr = 0; rr < 2; rr++) {
                    int row = grow + rr * 8;
                    int t = row >> 1, b_ = row & 1;
                    size_t idx = (((size_t)(b_ * 16 + hh)) * SEQ + t) * 64 + dd;
                    float v0 = (acc[mt][nt][rr * 2]     + b0) * scl;
                    float v1 = (acc[mt][nt][rr * 2 + 1] + b1) * scl;
                    if (sec == 0) {
                        uint32_t hi, lo;
                        split2h(v0, v1, hi, lo);
                        *(uint32_t*)(qhi + idx) = hi;
                        *(uint32_t*)(qlo + idx) = lo;
                    } else {
                        *(uint32_t*)(dhi + idx) = pack2h(v0, v1);
                    }
                }
            }
        }
    }
}

// ---------------------------------------------------------------------------
// Flash attention: fp16 2-MMA split (q,P split; k,v single), fp32 softmax.
// CTA: 128 queries x one (b,h). 8 warps x 16 rows. 64-key tiles, 3-stage
// KV ring, one barrier per k-tile. Output: split fp16 ctx [m][1024].
// ---------------------------------------------------------------------------
#define FQ_HI 0
#define FQ_LO 18432
#define FKV_O 36864
#define FKV_STAGE 18432                // kh 0 | vh 9216
#define FSMEM_TOTAL (FKV_O + 3 * FKV_STAGE)  // 92160

__global__ __launch_bounds__(256) void flash_mma(
    const __half* __restrict__ qhi, const __half* __restrict__ qlo,
    const __half* __restrict__ kh, const __half* __restrict__ vh,
    __half* __restrict__ chi, __half* __restrict__ clo,
    int nqt)
{
    extern __shared__ char smem[];
    const uint32_t sb = smem_to_u32(smem);
    const int tid  = threadIdx.x;
    const int wid  = tid >> 5;
    const int lane = tid & 31;

    const int bx = blockIdx.x;
    const int bh_ = bx & 31;                // b*16 + h
    const int qt = nqt - 1 - (bx >> 5);     // big tiles first
    const int b_ = bh_ >> 4;
    const int h  = bh_ & 15;
    const int t0 = qt * 128;
    const int nkt = 2 * (qt + 1);
    const size_t hb = ((size_t)(b_ * 16 + h)) * SEQ * 64;

#pragma unroll
    for (int c = tid; c < 2048; c += 256) {
        int tile = c >> 10, r = (c >> 3) & 127, ck = c & 7;
        const __half* src = (tile ? qlo : qhi) + hb + (size_t)(t0 + r) * 64 + ck * 8;
        cp_async16(sb + (tile ? FQ_LO : FQ_HI) + r * 144 + ck * 16, src);
    }
    const __half* kvsrc[2] = {kh, vh};
    auto kv_stage = [&](int kt) -> uint32_t {
        return sb + FKV_O + (kt % 3) * FKV_STAGE;
    };
    auto load_kv = [&](int kt) {
        uint32_t st = kv_stage(kt);
        int kt0 = kt * 64;
#pragma unroll
        for (int c = tid; c < 1024; c += 256) {
            int tile = c >> 9, r = (c >> 3) & 63, ck = c & 7;
            cp_async16(st + tile * 9216 + r * 144 + ck * 16,
                       kvsrc[tile] + hb + (size_t)(kt0 + r) * 64 + ck * 8);
        }
    };
    load_kv(0); CP_COMMIT();
    if (nkt > 1) { load_kv(1); CP_COMMIT(); }

    float o[8][4];
#pragma unroll
    for (int nt = 0; nt < 8; nt++)
#pragma unroll
        for (int i = 0; i < 4; i++) o[nt][i] = 0.f;
    float m0 = -1e30f, m1 = -1e30f, l0 = 0.f, l1 = 0.f;

    const int lrow = lane & 15;
    const int lcol = (lane >> 4) * 8;
    const int g    = lane >> 2;
    const int tig  = lane & 3;
    const int wq0  = wid * 16;
    const int row0 = t0 + wq0 + g;
    const int row1 = row0 + 8;

    for (int kt = 0; kt < nkt; kt++) {
        if (kt + 1 < nkt) { CP_WAIT(1); } else { CP_WAIT(0); }
        __syncthreads();          // single barrier per k-tile
        const int kt0 = kt * 64;
        const uint32_t st = kv_stage(kt);

        if (kt0 <= t0 + wq0 + 15) {
            // ---- S = Q @ K^T (2-MMA split: qh + ql, k single) ----
            float s[8][4];
#pragma unroll
            for (int nt = 0; nt < 8; nt++)
#pragma unroll
                for (int i = 0; i < 4; i++) s[nt][i] = 0.f;

#pragma unroll
            for (int ks = 0; ks < 4; ks++) {
                uint32_t ah[4], al[4];
                uint32_t qoff = (wq0 + lrow) * 144 + ks * 32 + lcol * 2;
                ldsm_x4(ah[0], ah[1], ah[2], ah[3], sb + FQ_HI + qoff);
                ldsm_x4(al[0], al[1], al[2], al[3], sb + FQ_LO + qoff);
                uint32_t bkh[8][2];
#pragma unroll
                for (int np = 0; np < 4; np++) {
                    uint32_t koff = (np * 16 + lrow) * 144 + ks * 32 + lcol * 2;
                    uint32_t r0, r1, r2, r3;
                    ldsm_x4(r0, r1, r2, r3, st + koff);
                    bkh[np * 2][0] = r0; bkh[np * 2][1] = r2;
                    bkh[np * 2 + 1][0] = r1; bkh[np * 2 + 1][1] = r3;
                }
#pragma unroll
                for (int nt = 0; nt < 8; nt++) {
                    mma_f16(s[nt], ah, bkh[nt]);
                    mma_f16(s[nt], al, bkh[nt]);
                }
            }

            // ---- causal mask (diagonal band only) ----
            if (kt0 + 63 > t0 + wq0) {
#pragma unroll
                for (int nt = 0; nt < 8; nt++) {
                    int col = kt0 + nt * 8 + tig * 2;
                    if (col     > row0) s[nt][0] = -1e30f;
                    if (col + 1 > row0) s[nt][1] = -1e30f;
                    if (col     > row1) s[nt][2] = -1e30f;
                    if (col + 1 > row1) s[nt][3] = -1e30f;
                }
            }

            // ---- online softmax (fp32) ----
            float mx0 = -1e30f, mx1 = -1e30f;
#pragma unroll
            for (int nt = 0; nt < 8; nt++) {
                mx0 = fmaxf(mx0, fmaxf(s[nt][0], s[nt][1]));
                mx1 = fmaxf(mx1, fmaxf(s[nt][2], s[nt][3]));
            }
#pragma unroll
            for (int off = 1; off < 4; off <<= 1) {
                mx0 = fmaxf(mx0, __shfl_xor_sync(0xFFFFFFFFu, mx0, off));
                mx1 = fmaxf(mx1, __shfl_xor_sync(0xFFFFFFFFu, mx1, off));
            }
            float nm0 = fmaxf(m0, mx0), nm1 = fmaxf(m1, mx1);
            float a0 = __expf(m0 - nm0), a1 = __expf(m1 - nm1);
            float sum0 = 0.f, sum1 = 0.f;
#pragma unroll
            for (int nt = 0; nt < 8; nt++) {
                s[nt][0] = __expf(s[nt][0] - nm0);
                s[nt][1] = __expf(s[nt][1] - nm0);
                s[nt][2] = __expf(s[nt][2] - nm1);
                s[nt][3] = __expf(s[nt][3] - nm1);
                sum0 += s[nt][0] + s[nt][1];
                sum1 += s[nt][2] + s[nt][3];
            }
#pragma unroll
            for (int off = 1; off < 4; off <<= 1) {
                sum0 += __shfl_xor_sync(0xFFFFFFFFu, sum0, off);
                sum1 += __shfl_xor_sync(0xFFFFFFFFu, sum1, off);
            }
            l0 = l0 * a0 + sum0;
            l1 = l1 * a1 + sum1;
            m0 = nm0; m1 = nm1;
#pragma unroll
            for (int nt = 0; nt < 8; nt++) {
                o[nt][0] *= a0; o[nt][1] *= a0;
                o[nt][2] *= a1; o[nt][3] *= a1;
            }

            // ---- pack P fragments (split fp16) ----
            uint32_t ph[4][4], pl[4][4];
#pragma unroll
            for (int ks = 0; ks < 4; ks++) {
                split2h(s[2 * ks][0],     s[2 * ks][1],     ph[ks][0], pl[ks][0]);
                split2h(s[2 * ks][2],     s[2 * ks][3],     ph[ks][1], pl[ks][1]);
                split2h(s[2 * ks + 1][0], s[2 * ks + 1][1], ph[ks][2], pl[ks][2]);
                split2h(s[2 * ks + 1][2], s[2 * ks + 1][3], ph[ks][3], pl[ks][3]);
            }

            // ---- O += P @ V (2-MMA split: ph + pl, v single) ----
#pragma unroll
            for (int ks = 0; ks < 4; ks++) {
                uint32_t bvh[8][2];
#pragma unroll
                for (int db = 0; db < 4; db++) {
                    uint32_t voff = (ks * 16 + lrow) * 144 + db * 32 + lcol * 2;
                    uint32_t r0, r1, r2, r3;
                    ldsm_x4_t(r0, r1, r2, r3, st + 9216 + voff);
                    bvh[db * 2][0] = r0; bvh[db * 2][1] = r1;
                    bvh[db * 2 + 1][0] = r2; bvh[db * 2 + 1][1] = r3;
                }
#pragma unroll
                for (int nt = 0; nt < 8; nt++) {
                    mma_f16(o[nt], ph[ks], bvh[nt]);
                    mma_f16(o[nt], pl[ks], bvh[nt]);
                }
            }
        }
        if (kt + 2 < nkt) { load_kv(kt + 2); CP_COMMIT(); }
    }

    // ---- epilogue: ctx split fp16, [m = t*B + b_][h*64 + d] ----
    const float i0 = 1.f / l0;
    const float i1 = 1.f / l1;
#pragma unroll
    for (int nt = 0; nt < 8; nt++) {
        const int d = nt * 8 + tig * 2;
        size_t o0 = ((size_t)(row0 * BATCH + b_)) * D_MODEL + h * 64 + d;
        size_t o1 = ((size_t)(row1 * BATCH + b_)) * D_MODEL + h * 64 + d;
        uint32_t hi, lo;
        split2h(o[nt][0] * i0, o[nt][1] * i0, hi, lo);
        *(uint32_t*)(chi + o0) = hi;
        *(uint32_t*)(clo + o0) = lo;
        split2h(o[nt][2] * i1, o[nt][3] * i1, hi, lo);
        *(uint32_t*)(chi + o1) = hi;
        *(uint32_t*)(clo + o1) = lo;
    }
}

// ---------------------------------------------------------------------------
extern "C" void kernel_launch(void* const* d_in, const int* in_sizes, int n_in,
                              void* d_out, int out_size)
{
    const float* x    = (const float*)d_in[0];
    const float* Wqkv = (const float*)d_in[1];
    const float* bqkv = (const float*)d_in[2];
    const float* Wout = (const float*)d_in[3];
    const float* bout = (const float*)d_in[4];
    float* out = (float*)d_out;

    const int M = in_sizes[0] / D_MODEL;   // 4096
    const int T = M / BATCH;               // 2048
    const int nqt = T / 128;               // 16

    __half *xhi, *xlo, *w1h, *w2h, *chi, *clo, *qhi, *qlo, *kh, *vh;
    cudaGetSymbolAddress((void**)&xhi, g_xhi);
    cudaGetSymbolAddress((void**)&xlo, g_xlo);
    cudaGetSymbolAddress((void**)&w1h, g_w1h);
    cudaGetSymbolAddress((void**)&w2h, g_w2h);
    cudaGetSymbolAddress((void**)&chi, g_chi);
    cudaGetSymbolAddress((void**)&clo, g_clo);
    cudaGetSymbolAddress((void**)&qhi, g_qhi);
    cudaGetSymbolAddress((void**)&qlo, g_qlo);
    cudaGetSymbolAddress((void**)&kh, g_kh);
    cudaGetSymbolAddress((void**)&vh, g_vh);

    cudaFuncSetAttribute(gemm_mma<0>, cudaFuncAttributeMaxDynamicSharedMemorySize, GSMEM_TOTAL);
    cudaFuncSetAttribute(gemm_mma<1>, cudaFuncAttributeMaxDynamicSharedMemorySize, GSMEM_TOTAL);
    cudaFuncSetAttribute(flash_mma, cudaFuncAttributeMaxDynamicSharedMemorySize, FSMEM_TOTAL);

    // 1) convert inputs
    split_convert<<<(M * D_MODEL / 4 + 255) / 256, 256>>>(x, xhi, xlo, M * D_MODEL / 4);
    convert_T<<<dim3(3 * D_MODEL / 32, D_MODEL / 32), dim3(32, 8)>>>(
        Wqkv, w1h, D_MODEL, 3 * D_MODEL);

    // 2) QKV projection -> q split + k/v fp16 in [B,H,T,64]
    gemm_mma<1><<<dim3(3 * D_MODEL / 128, M / 128), 256, GSMEM_TOTAL>>>(
        xhi, xlo, w1h, bqkv, nullptr,
        qhi, qlo, kh, vh, M, 3 * D_MODEL, D_MODEL);

    // 3) causal flash attention -> split fp16 ctx
    flash_mma<<<32 * nqt, 256, FSMEM_TOTAL>>>(qhi, qlo, kh, vh, chi, clo, nqt);

    // 4) output projection
    convert_T<<<dim3(D_MODEL / 32, D_MODEL / 32), dim3(32, 8)>>>(
        Wout, w2h, D_MODEL, D_MODEL);
    gemm_mma<0><<<dim3(D_MODEL / 128, M / 128), 256, GSMEM_TOTAL>>>(
        chi, clo, w2h, bout, out,
        nullptr, nullptr, nullptr, nullptr, M, D_MODEL, D_MODEL);
}

// round 8
// speedup vs baseline: 4.6192x; 1.0241x over previous
#include <cuda_runtime.h>
#include <cuda_fp16.h>
#include <cstdint>
#include <math.h>

#define D_MODEL 1024
#define N_HEADS 16
#define HEAD_DIM 64
#define BATCH 2
#define SEQ 2048

// ---------------------------------------------------------------------------
// Scratch (allocation-free rule: __device__ globals)
// ---------------------------------------------------------------------------
__device__ __half g_xhi[4096 * 1024];        // x split (fp16 hi/lo)
__device__ __half g_xlo[4096 * 1024];
__device__ __half g_w1h[3072 * 1024];        // Wqkv^T fp16  [N,K]
__device__ __half g_w2h[1024 * 1024];        // Wout^T fp16  [N,K]
// q split, k/v single fp16, [B,H,T,64] (q prescaled by 0.125)
__device__ __half g_qhi[BATCH * N_HEADS * SEQ * 64];
__device__ __half g_qlo[BATCH * N_HEADS * SEQ * 64];
__device__ __half g_kh[BATCH * N_HEADS * SEQ * 64];
__device__ __half g_vh[BATCH * N_HEADS * SEQ * 64];
// attention output (ctx) split fp16, [m=T*B rows][1024]
__device__ __half g_chi[4096 * 1024];
__device__ __half g_clo[4096 * 1024];

// ---------------------------------------------------------------------------
// PTX helpers (plain sm_103-compatible: mma.sync / ldmatrix / cp.async)
// ---------------------------------------------------------------------------
__device__ __forceinline__ uint32_t smem_to_u32(const void* p) {
    uint32_t a;
    asm("{ .reg .u64 t; cvta.to.shared.u64 t, %1; cvt.u32.u64 %0, t; }" : "=r"(a) : "l"(p));
    return a;
}
__device__ __forceinline__ void cp_async16(uint32_t dst, const void* src) {
    asm volatile("cp.async.cg.shared.global [%0], [%1], 16;" :: "r"(dst), "l"(src) : "memory");
}
#define CP_COMMIT() asm volatile("cp.async.commit_group;" ::: "memory")
#define CP_WAIT(n)  asm volatile("cp.async.wait_group %0;" :: "n"(n) : "memory")

__device__ __forceinline__ void ldsm_x4(uint32_t& r0, uint32_t& r1, uint32_t& r2, uint32_t& r3,
                                        uint32_t addr) {
    asm volatile("ldmatrix.sync.aligned.m8n8.x4.shared.b16 {%0,%1,%2,%3}, [%4];"
                 : "=r"(r0), "=r"(r1), "=r"(r2), "=r"(r3) : "r"(addr));
}
__device__ __forceinline__ void ldsm_x4_t(uint32_t& r0, uint32_t& r1, uint32_t& r2, uint32_t& r3,
                                          uint32_t addr) {
    asm volatile("ldmatrix.sync.aligned.m8n8.x4.trans.shared.b16 {%0,%1,%2,%3}, [%4];"
                 : "=r"(r0), "=r"(r1), "=r"(r2), "=r"(r3) : "r"(addr));
}
__device__ __forceinline__ void mma_f16(float c[4], const uint32_t a[4], const uint32_t b[2]) {
    asm volatile(
        "mma.sync.aligned.m16n8k16.row.col.f32.f16.f16.f32 "
        "{%0,%1,%2,%3}, {%4,%5,%6,%7}, {%8,%9}, {%0,%1,%2,%3};"
        : "+f"(c[0]), "+f"(c[1]), "+f"(c[2]), "+f"(c[3])
        : "r"(a[0]), "r"(a[1]), "r"(a[2]), "r"(a[3]), "r"(b[0]), "r"(b[1]));
}

__device__ __forceinline__ void split2h(float x, float y, uint32_t& hi, uint32_t& lo) {
    __half hx = __float2half(x), hy = __float2half(y);
    __half2 h2 = __halves2half2(hx, hy);
    __half2 l2 = __halves2half2(
        __float2half(x - __half2float(hx)),
        __float2half(y - __half2float(hy)));
    hi = *(uint32_t*)&h2;
    lo = *(uint32_t*)&l2;
}
__device__ __forceinline__ uint32_t pack2h(float x, float y) {
    __half2 h2 = __halves2half2(__float2half(x), __float2half(y));
    return *(uint32_t*)&h2;
}

// ---------------------------------------------------------------------------
// Conversion kernels
// ---------------------------------------------------------------------------
__global__ __launch_bounds__(256) void split_convert(
    const float* __restrict__ in, __half* __restrict__ hi,
    __half* __restrict__ lo, int n4)
{
    int i = blockIdx.x * blockDim.x + threadIdx.x;
    if (i >= n4) return;
    float4 v = ((const float4*)in)[i];
    __half h0 = __float2half(v.x), h1 = __float2half(v.y);
    __half h2 = __float2half(v.z), h3 = __float2half(v.w);
    __half l0 = __float2half(v.x - __half2float(h0));
    __half l1 = __float2half(v.y - __half2float(h1));
    __half l2 = __float2half(v.z - __half2float(h2));
    __half l3 = __float2half(v.w - __half2float(h3));
    ((__half2*)hi)[i * 2]     = __halves2half2(h0, h1);
    ((__half2*)hi)[i * 2 + 1] = __halves2half2(h2, h3);
    ((__half2*)lo)[i * 2]     = __halves2half2(l0, l1);
    ((__half2*)lo)[i * 2 + 1] = __halves2half2(l2, l3);
}

// W[K,N] fp32 -> Wt [N,K] fp16 (transpose, round-to-nearest). 32x32 tiles.
__global__ __launch_bounds__(256) void convert_T(
    const float* __restrict__ W, __half* __restrict__ hi, int K, int N)
{
    __shared__ float t[32][33];
    const int n0 = blockIdx.x * 32;
    const int k0 = blockIdx.y * 32;
#pragma unroll
    for (int i = 0; i < 4; i++) {
        int k = k0 + threadIdx.y + i * 8;
        t[threadIdx.y + i * 8][threadIdx.x] = W[(size_t)k * N + n0 + threadIdx.x];
    }
    __syncthreads();
#pragma unroll
    for (int i = 0; i < 4; i++) {
        int nn = n0 + threadIdx.y + i * 8;
        hi[(size_t)nn * K + k0 + threadIdx.x] = __float2half(t[threadIdx.x][threadIdx.y + i * 8]);
    }
}

// ---------------------------------------------------------------------------
// fp16 2-MMA split GEMM: C = (Ahi+Alo)[M,K] @ Bh[N,K]^T + bias
// 3-stage cp.async ring, prefetch issued right after the barrier.
// MODE 0: fp32 C. MODE 1: QKV epilogue -> q split fp16 + k/v fp16 [B,H,T,64].
// ---------------------------------------------------------------------------
#define BK 32
#define ASTRIDE 40                     // fp16 elems per smem row (32 + 8 pad)
#define TILE_BYTES (128 * ASTRIDE * 2) // 10240
#define T_AHI 0
#define T_ALO (1 * TILE_BYTES)
#define T_BH  (2 * TILE_BYTES)
#define STAGE_BYTES (3 * TILE_BYTES)   // 30720
#define GSMEM_TOTAL (3 * STAGE_BYTES)  // 92160

template <int MODE>
__global__ __launch_bounds__(256, 2) void gemm_mma(
    const __half* __restrict__ Ahi, const __half* __restrict__ Alo,
    const __half* __restrict__ Bh,
    const float* __restrict__ bias, float* __restrict__ C,
    __half* __restrict__ qhi, __half* __restrict__ qlo,
    __half* __restrict__ kh, __half* __restrict__ vh,
    int M, int N, int K)
{
    extern __shared__ char smem[];
    const uint32_t smem_base = smem_to_u32(smem);
    const int tid  = threadIdx.x;
    const int wid  = tid >> 5;
    const int lane = tid & 31;
    const int bm = blockIdx.y * 128;
    const int bn = blockIdx.x * 128;
    const int wm = (wid & 3) * 32;
    const int wn = (wid >> 2) * 64;

    const __half* srcs[3] = {Ahi, Alo, Bh};
    const int rows0[3]    = {bm, bm, bn};

    auto load_stage = [&](int it) {
        const uint32_t sb = smem_base + (it % 3) * STAGE_BYTES;
        const int k0 = it * BK;
#pragma unroll
        for (int c = tid; c < 1536; c += 256) {
            int mat = c >> 9;
            int r   = (c >> 2) & 127;
            int kc  = (c & 3) * 8;
            const __half* src = srcs[mat] + (size_t)(rows0[mat] + r) * K + k0 + kc;
            uint32_t dst = sb + mat * TILE_BYTES + (r * ASTRIDE + kc) * 2;
            cp_async16(dst, src);
        }
    };

    const int NK = K / BK;
    load_stage(0); CP_COMMIT();
    load_stage(1); CP_COMMIT();

    float acc[2][8][4];
#pragma unroll
    for (int mt = 0; mt < 2; mt++)
#pragma unroll
        for (int nt = 0; nt < 8; nt++)
#pragma unroll
            for (int i = 0; i < 4; i++) acc[mt][nt][i] = 0.f;

    const int lrow = lane & 15;
    const int lcol = (lane >> 4) * 8;

    for (int kt = 0; kt < NK; kt++) {
        if (kt + 1 < NK) { CP_WAIT(1); } else { CP_WAIT(0); }
        __syncthreads();       // single barrier per kt (3-stage ring)
        // prefetch issued BEFORE compute: stage (kt+2)%3 was freed at kt-1
        if (kt + 2 < NK) { load_stage(kt + 2); CP_COMMIT(); }
        const uint32_t sb = smem_base + (kt % 3) * STAGE_BYTES;

#pragma unroll
        for (int ks = 0; ks < 2; ks++) {
            uint32_t ah[2][4], al[2][4];
#pragma unroll
            for (int mt = 0; mt < 2; mt++) {
                uint32_t off = ((wm + mt * 16 + lrow) * ASTRIDE + ks * 16 + lcol) * 2;
                ldsm_x4(ah[mt][0], ah[mt][1], ah[mt][2], ah[mt][3], sb + T_AHI + off);
                ldsm_x4(al[mt][0], al[mt][1], al[mt][2], al[mt][3], sb + T_ALO + off);
            }
            uint32_t bh[8][2];
#pragma unroll
            for (int np = 0; np < 4; np++) {
                uint32_t off = ((wn + np * 16 + lrow) * ASTRIDE + ks * 16 + lcol) * 2;
                uint32_t r0, r1, r2, r3;
                ldsm_x4(r0, r1, r2, r3, sb + T_BH + off);
                bh[np * 2][0] = r0; bh[np * 2][1] = r2;
                bh[np * 2 + 1][0] = r1; bh[np * 2 + 1][1] = r3;
            }
#pragma unroll
            for (int mt = 0; mt < 2; mt++)
#pragma unroll
                for (int nt = 0; nt < 8; nt++) {
                    mma_f16(acc[mt][nt], ah[mt], bh[nt]);
                    mma_f16(acc[mt][nt], al[mt], bh[nt]);
                }
        }
    }

    const int trow = lane >> 2;
    const int tcol = (lane & 3) * 2;

    if (MODE == 0) {
#pragma unroll
        for (int mt = 0; mt < 2; mt++) {
            const int grow = bm + wm + mt * 16 + trow;
#pragma unroll
            for (int nt = 0; nt < 8; nt++) {
                const int gcol = bn + wn + nt * 8 + tcol;
                float b0 = bias[gcol], b1 = bias[gcol + 1];
                float2 o0 = {acc[mt][nt][0] + b0, acc[mt][nt][1] + b1};
                float2 o1 = {acc[mt][nt][2] + b0, acc[mt][nt][3] + b1};
                *(float2*)(C + (size_t)grow * N + gcol)       = o0;
                *(float2*)(C + (size_t)(grow + 8) * N + gcol) = o1;
            }
        }
    } else {
        const int sec = bn >> 10;   // 0:q 1:k 2:v (uniform per CTA)
        __half* dhi = (sec == 0) ? qhi : (sec == 1) ? kh : vh;
        const float scl = (sec == 0) ? 0.125f : 1.f;
#pragma unroll
        for (int mt = 0; mt < 2; mt++) {
            const int grow = bm + wm + mt * 16 + trow;
#pragma unroll
            for (int nt = 0; nt < 8; nt++) {
                const int gcol = bn + wn + nt * 8 + tcol;
                const int hh = (gcol >> 6) & 15;
                const int dd = gcol & 63;
                float b0 = bias[gcol], b1 = bias[gcol + 1];
#pragma unroll
                for (int rr = 0; rr < 2; rr++) {
                    int row = grow + rr * 8;
                    int t = row >> 1, b_ = row & 1;
                    size_t idx = (((size_t)(b_ * 16 + hh)) * SEQ + t) * 64 + dd;
                    float v0 = (acc[mt][nt][rr * 2]     + b0) * scl;
                    float v1 = (acc[mt][nt][rr * 2 + 1] + b1) * scl;
                    if (sec == 0) {
                        uint32_t hi, lo;
                        split2h(v0, v1, hi, lo);
                        *(uint32_t*)(qhi + idx) = hi;
                        *(uint32_t*)(qlo + idx) = lo;
                    } else {
                        *(uint32_t*)(dhi + idx) = pack2h(v0, v1);
                    }
                }
            }
        }
    }
}

// ---------------------------------------------------------------------------
// Flash attention: q split (2-MMA QK), P single fp16 (1-MMA PV), fp32 softmax.
// CTA: 128 queries x one (b,h). 8 warps x 16 rows. 64-key tiles, 3-stage
// KV ring, one barrier per k-tile, prefetch right after barrier.
// Output: split fp16 ctx [m][1024].
// ---------------------------------------------------------------------------
#define FQ_HI 0
#define FQ_LO 18432
#define FKV_O 36864
#define FKV_STAGE 18432                // kh 0 | vh 9216
#define FSMEM_TOTAL (FKV_O + 3 * FKV_STAGE)  // 92160

__global__ __launch_bounds__(256) void flash_mma(
    const __half* __restrict__ qhi, const __half* __restrict__ qlo,
    const __half* __restrict__ kh, const __half* __restrict__ vh,
    __half* __restrict__ chi, __half* __restrict__ clo,
    int nqt)
{
    extern __shared__ char smem[];
    const uint32_t sb = smem_to_u32(smem);
    const int tid  = threadIdx.x;
    const int wid  = tid >> 5;
    const int lane = tid & 31;

    const int bx = blockIdx.x;
    const int bh_ = bx & 31;                // b*16 + h
    const int qt = nqt - 1 - (bx >> 5);     // big tiles first
    const int b_ = bh_ >> 4;
    const int h  = bh_ & 15;
    const int t0 = qt * 128;
    const int nkt = 2 * (qt + 1);
    const size_t hb = ((size_t)(b_ * 16 + h)) * SEQ * 64;

#pragma unroll
    for (int c = tid; c < 2048; c += 256) {
        int tile = c >> 10, r = (c >> 3) & 127, ck = c & 7;
        const __half* src = (tile ? qlo : qhi) + hb + (size_t)(t0 + r) * 64 + ck * 8;
        cp_async16(sb + (tile ? FQ_LO : FQ_HI) + r * 144 + ck * 16, src);
    }
    const __half* kvsrc[2] = {kh, vh};
    auto kv_stage = [&](int kt) -> uint32_t {
        return sb + FKV_O + (kt % 3) * FKV_STAGE;
    };
    auto load_kv = [&](int kt) {
        uint32_t st = kv_stage(kt);
        int kt0 = kt * 64;
#pragma unroll
        for (int c = tid; c < 1024; c += 256) {
            int tile = c >> 9, r = (c >> 3) & 63, ck = c & 7;
            cp_async16(st + tile * 9216 + r * 144 + ck * 16,
                       kvsrc[tile] + hb + (size_t)(kt0 + r) * 64 + ck * 8);
        }
    };
    load_kv(0); CP_COMMIT();
    if (nkt > 1) { load_kv(1); CP_COMMIT(); }

    float o[8][4];
#pragma unroll
    for (int nt = 0; nt < 8; nt++)
#pragma unroll
        for (int i = 0; i < 4; i++) o[nt][i] = 0.f;
    float m0 = -1e30f, m1 = -1e30f, l0 = 0.f, l1 = 0.f;

    const int lrow = lane & 15;
    const int lcol = (lane >> 4) * 8;
    const int g    = lane >> 2;
    const int tig  = lane & 3;
    const int wq0  = wid * 16;
    const int row0 = t0 + wq0 + g;
    const int row1 = row0 + 8;

    for (int kt = 0; kt < nkt; kt++) {
        if (kt + 1 < nkt) { CP_WAIT(1); } else { CP_WAIT(0); }
        __syncthreads();          // single barrier per k-tile
        // prefetch issued BEFORE compute: stage (kt+2)%3 was freed at kt-1
        if (kt + 2 < nkt) { load_kv(kt + 2); CP_COMMIT(); }
        const int kt0 = kt * 64;
        const uint32_t st = kv_stage(kt);

        if (kt0 <= t0 + wq0 + 15) {
            // ---- S = Q @ K^T (2-MMA split: qh + ql, k single) ----
            float s[8][4];
#pragma unroll
            for (int nt = 0; nt < 8; nt++)
#pragma unroll
                for (int i = 0; i < 4; i++) s[nt][i] = 0.f;

#pragma unroll
            for (int ks = 0; ks < 4; ks++) {
                uint32_t ah[4], al[4];
                uint32_t qoff = (wq0 + lrow) * 144 + ks * 32 + lcol * 2;
                ldsm_x4(ah[0], ah[1], ah[2], ah[3], sb + FQ_HI + qoff);
                ldsm_x4(al[0], al[1], al[2], al[3], sb + FQ_LO + qoff);
                uint32_t bkh[8][2];
#pragma unroll
                for (int np = 0; np < 4; np++) {
                    uint32_t koff = (np * 16 + lrow) * 144 + ks * 32 + lcol * 2;
                    uint32_t r0, r1, r2, r3;
                    ldsm_x4(r0, r1, r2, r3, st + koff);
                    bkh[np * 2][0] = r0; bkh[np * 2][1] = r2;
                    bkh[np * 2 + 1][0] = r1; bkh[np * 2 + 1][1] = r3;
                }
#pragma unroll
                for (int nt = 0; nt < 8; nt++) {
                    mma_f16(s[nt], ah, bkh[nt]);
                    mma_f16(s[nt], al, bkh[nt]);
                }
            }

            // ---- causal mask (diagonal band only) ----
            if (kt0 + 63 > t0 + wq0) {
#pragma unroll
                for (int nt = 0; nt < 8; nt++) {
                    int col = kt0 + nt * 8 + tig * 2;
                    if (col     > row0) s[nt][0] = -1e30f;
                    if (col + 1 > row0) s[nt][1] = -1e30f;
                    if (col     > row1) s[nt][2] = -1e30f;
                    if (col + 1 > row1) s[nt][3] = -1e30f;
                }
            }

            // ---- online softmax (fp32) ----
            float mx0 = -1e30f, mx1 = -1e30f;
#pragma unroll
            for (int nt = 0; nt < 8; nt++) {
                mx0 = fmaxf(mx0, fmaxf(s[nt][0], s[nt][1]));
                mx1 = fmaxf(mx1, fmaxf(s[nt][2], s[nt][3]));
            }
#pragma unroll
            for (int off = 1; off < 4; off <<= 1) {
                mx0 = fmaxf(mx0, __shfl_xor_sync(0xFFFFFFFFu, mx0, off));
                mx1 = fmaxf(mx1, __shfl_xor_sync(0xFFFFFFFFu, mx1, off));
            }
            float nm0 = fmaxf(m0, mx0), nm1 = fmaxf(m1, mx1);
            float a0 = __expf(m0 - nm0), a1 = __expf(m1 - nm1);
            float sum0 = 0.f, sum1 = 0.f;
#pragma unroll
            for (int nt = 0; nt < 8; nt++) {
                s[nt][0] = __expf(s[nt][0] - nm0);
                s[nt][1] = __expf(s[nt][1] - nm0);
                s[nt][2] = __expf(s[nt][2] - nm1);
                s[nt][3] = __expf(s[nt][3] - nm1);
                sum0 += s[nt][0] + s[nt][1];
                sum1 += s[nt][2] + s[nt][3];
            }
#pragma unroll
            for (int off = 1; off < 4; off <<= 1) {
                sum0 += __shfl_xor_sync(0xFFFFFFFFu, sum0, off);
                sum1 += __shfl_xor_sync(0xFFFFFFFFu, sum1, off);
            }
            l0 = l0 * a0 + sum0;
            l1 = l1 * a1 + sum1;
            m0 = nm0; m1 = nm1;
#pragma unroll
            for (int nt = 0; nt < 8; nt++) {
                o[nt][0] *= a0; o[nt][1] *= a0;
                o[nt][2] *= a1; o[nt][3] *= a1;
            }

            // ---- pack P fragments (single fp16) ----
            uint32_t ph[4][4];
#pragma unroll
            for (int ks = 0; ks < 4; ks++) {
                ph[ks][0] = pack2h(s[2 * ks][0],     s[2 * ks][1]);
                ph[ks][1] = pack2h(s[2 * ks][2],     s[2 * ks][3]);
                ph[ks][2] = pack2h(s[2 * ks + 1][0], s[2 * ks + 1][1]);
                ph[ks][3] = pack2h(s[2 * ks + 1][2], s[2 * ks + 1][3]);
            }

            // ---- O += P @ V (single MMA, V via ldmatrix.trans) ----
#pragma unroll
            for (int ks = 0; ks < 4; ks++) {
                uint32_t bvh[8][2];
#pragma unroll
                for (int db = 0; db < 4; db++) {
                    uint32_t voff = (ks * 16 + lrow) * 144 + db * 32 + lcol * 2;
                    uint32_t r0, r1, r2, r3;
                    ldsm_x4_t(r0, r1, r2, r3, st + 9216 + voff);
                    bvh[db * 2][0] = r0; bvh[db * 2][1] = r1;
                    bvh[db * 2 + 1][0] = r2; bvh[db * 2 + 1][1] = r3;
                }
#pragma unroll
                for (int nt = 0; nt < 8; nt++) {
                    mma_f16(o[nt], ph[ks], bvh[nt]);
                }
            }
        }
    }

    // ---- epilogue: ctx split fp16, [m = t*B + b_][h*64 + d] ----
    const float i0 = 1.f / l0;
    const float i1 = 1.f / l1;
#pragma unroll
    for (int nt = 0; nt < 8; nt++) {
        const int d = nt * 8 + tig * 2;
        size_t o0 = ((size_t)(row0 * BATCH + b_)) * D_MODEL + h * 64 + d;
        size_t o1 = ((size_t)(row1 * BATCH + b_)) * D_MODEL + h * 64 + d;
        uint32_t hi, lo;
        split2h(o[nt][0] * i0, o[nt][1] * i0, hi, lo);
        *(uint32_t*)(chi + o0) = hi;
        *(uint32_t*)(clo + o0) = lo;
        split2h(o[nt][2] * i1, o[nt][3] * i1, hi, lo);
        *(uint32_t*)(chi + o1) = hi;
        *(uint32_t*)(clo + o1) = lo;
    }
}

// ---------------------------------------------------------------------------
extern "C" void kernel_launch(void* const* d_in, const int* in_sizes, int n_in,
                              void* d_out, int out_size)
{
    const float* x    = (const float*)d_in[0];
    const float* Wqkv = (const float*)d_in[1];
    const float* bqkv = (const float*)d_in[2];
    const float* Wout = (const float*)d_in[3];
    const float* bout = (const float*)d_in[4];
    float* out = (float*)d_out;

    const int M = in_sizes[0] / D_MODEL;   // 4096
    const int T = M / BATCH;               // 2048
    const int nqt = T / 128;               // 16

    __half *xhi, *xlo, *w1h, *w2h, *chi, *clo, *qhi, *qlo, *kh, *vh;
    cudaGetSymbolAddress((void**)&xhi, g_xhi);
    cudaGetSymbolAddress((void**)&xlo, g_xlo);
    cudaGetSymbolAddress((void**)&w1h, g_w1h);
    cudaGetSymbolAddress((void**)&w2h, g_w2h);
    cudaGetSymbolAddress((void**)&chi, g_chi);
    cudaGetSymbolAddress((void**)&clo, g_clo);
    cudaGetSymbolAddress((void**)&qhi, g_qhi);
    cudaGetSymbolAddress((void**)&qlo, g_qlo);
    cudaGetSymbolAddress((void**)&kh, g_kh);
    cudaGetSymbolAddress((void**)&vh, g_vh);

    cudaFuncSetAttribute(gemm_mma<0>, cudaFuncAttributeMaxDynamicSharedMemorySize, GSMEM_TOTAL);
    cudaFuncSetAttribute(gemm_mma<1>, cudaFuncAttributeMaxDynamicSharedMemorySize, GSMEM_TOTAL);
    cudaFuncSetAttribute(flash_mma, cudaFuncAttributeMaxDynamicSharedMemorySize, FSMEM_TOTAL);

    // 1) convert inputs
    split_convert<<<(M * D_MODEL / 4 + 255) / 256, 256>>>(x, xhi, xlo, M * D_MODEL / 4);
    convert_T<<<dim3(3 * D_MODEL / 32, D_MODEL / 32), dim3(32, 8)>>>(
        Wqkv, w1h, D_MODEL, 3 * D_MODEL);

    // 2) QKV projection -> q split + k/v fp16 in [B,H,T,64]
    gemm_mma<1><<<dim3(3 * D_MODEL / 128, M / 128), 256, GSMEM_TOTAL>>>(
        xhi, xlo, w1h, bqkv, nullptr,
        qhi, qlo, kh, vh, M, 3 * D_MODEL, D_MODEL);

    // 3) causal flash attention -> split fp16 ctx
    flash_mma<<<32 * nqt, 256, FSMEM_TOTAL>>>(qhi, qlo, kh, vh, chi, clo, nqt);

    // 4) output projection
    convert_T<<<dim3(D_MODEL / 32, D_MODEL / 32), dim3(32, 8)>>>(
        Wout, w2h, D_MODEL, D_MODEL);
    gemm_mma<0><<<dim3(D_MODEL / 128, M / 128), 256, GSMEM_TOTAL>>>(
        chi, clo, w2h, bout, out,
        nullptr, nullptr, nullptr, nullptr, M, D_MODEL, D_MODEL);
}

// round 9
// speedup vs baseline: 4.6401x; 1.0045x over previous
#include <cuda_runtime.h>
#include <cuda_fp16.h>
#include <cstdint>
#include <math.h>

#define D_MODEL 1024
#define N_HEADS 16
#define HEAD_DIM 64
#define BATCH 2
#define SEQ 2048

// ---------------------------------------------------------------------------
// Scratch (allocation-free rule: __device__ globals)
// ---------------------------------------------------------------------------
__device__ __half g_xhi[4096 * 1024];        // x split (fp16 hi/lo)
__device__ __half g_xlo[4096 * 1024];
__device__ __half g_w1h[3072 * 1024];        // Wqkv^T fp16  [N,K]
__device__ __half g_w2h[1024 * 1024];        // Wout^T fp16  [N,K]
// q split, k/v single fp16, [B,H,T,64] (q prescaled by 0.125)
__device__ __half g_qhi[BATCH * N_HEADS * SEQ * 64];
__device__ __half g_qlo[BATCH * N_HEADS * SEQ * 64];
__device__ __half g_kh[BATCH * N_HEADS * SEQ * 64];
__device__ __half g_vh[BATCH * N_HEADS * SEQ * 64];
// attention output (ctx) split fp16, [m=T*B rows][1024]
__device__ __half g_chi[4096 * 1024];
__device__ __half g_clo[4096 * 1024];

// ---------------------------------------------------------------------------
// PTX helpers (plain sm_103-compatible: mma.sync / ldmatrix / cp.async)
// ---------------------------------------------------------------------------
__device__ __forceinline__ uint32_t smem_to_u32(const void* p) {
    uint32_t a;
    asm("{ .reg .u64 t; cvta.to.shared.u64 t, %1; cvt.u32.u64 %0, t; }" : "=r"(a) : "l"(p));
    return a;
}
__device__ __forceinline__ void cp_async16(uint32_t dst, const void* src) {
    asm volatile("cp.async.cg.shared.global [%0], [%1], 16;" :: "r"(dst), "l"(src) : "memory");
}
#define CP_COMMIT() asm volatile("cp.async.commit_group;" ::: "memory")
#define CP_WAIT(n)  asm volatile("cp.async.wait_group %0;" :: "n"(n) : "memory")

__device__ __forceinline__ void ldsm_x4(uint32_t& r0, uint32_t& r1, uint32_t& r2, uint32_t& r3,
                                        uint32_t addr) {
    asm volatile("ldmatrix.sync.aligned.m8n8.x4.shared.b16 {%0,%1,%2,%3}, [%4];"
                 : "=r"(r0), "=r"(r1), "=r"(r2), "=r"(r3) : "r"(addr));
}
__device__ __forceinline__ void ldsm_x4_t(uint32_t& r0, uint32_t& r1, uint32_t& r2, uint32_t& r3,
                                          uint32_t addr) {
    asm volatile("ldmatrix.sync.aligned.m8n8.x4.trans.shared.b16 {%0,%1,%2,%3}, [%4];"
                 : "=r"(r0), "=r"(r1), "=r"(r2), "=r"(r3) : "r"(addr));
}
__device__ __forceinline__ void mma_f16(float c[4], const uint32_t a[4], const uint32_t b[2]) {
    asm volatile(
        "mma.sync.aligned.m16n8k16.row.col.f32.f16.f16.f32 "
        "{%0,%1,%2,%3}, {%4,%5,%6,%7}, {%8,%9}, {%0,%1,%2,%3};"
        : "+f"(c[0]), "+f"(c[1]), "+f"(c[2]), "+f"(c[3])
        : "r"(a[0]), "r"(a[1]), "r"(a[2]), "r"(a[3]), "r"(b[0]), "r"(b[1]));
}

__device__ __forceinline__ void split2h(float x, float y, uint32_t& hi, uint32_t& lo) {
    __half hx = __float2half(x), hy = __float2half(y);
    __half2 h2 = __halves2half2(hx, hy);
    __half2 l2 = __halves2half2(
        __float2half(x - __half2float(hx)),
        __float2half(y - __half2float(hy)));
    hi = *(uint32_t*)&h2;
    lo = *(uint32_t*)&l2;
}
__device__ __forceinline__ uint32_t pack2h(float x, float y) {
    __half2 h2 = __halves2half2(__float2half(x), __float2half(y));
    return *(uint32_t*)&h2;
}
// exp2 of a pair, result as packed fp16x2 (input pre-scaled by log2e)
__device__ __forceinline__ uint32_t exp2h2(float x, float y) {
    __half2 h = __floats2half2_rn(x, y);
    uint32_t r = *(uint32_t*)&h;
    uint32_t d;
    asm("ex2.approx.f16x2 %0, %1;" : "=r"(d) : "r"(r));
    return d;
}

// ---------------------------------------------------------------------------
// Conversion kernels
// ---------------------------------------------------------------------------
__global__ __launch_bounds__(256) void split_convert(
    const float* __restrict__ in, __half* __restrict__ hi,
    __half* __restrict__ lo, int n4)
{
    int i = blockIdx.x * blockDim.x + threadIdx.x;
    if (i >= n4) return;
    float4 v = ((const float4*)in)[i];
    __half h0 = __float2half(v.x), h1 = __float2half(v.y);
    __half h2 = __float2half(v.z), h3 = __float2half(v.w);
    __half l0 = __float2half(v.x - __half2float(h0));
    __half l1 = __float2half(v.y - __half2float(h1));
    __half l2 = __float2half(v.z - __half2float(h2));
    __half l3 = __float2half(v.w - __half2float(h3));
    ((__half2*)hi)[i * 2]     = __halves2half2(h0, h1);
    ((__half2*)hi)[i * 2 + 1] = __halves2half2(h2, h3);
    ((__half2*)lo)[i * 2]     = __halves2half2(l0, l1);
    ((__half2*)lo)[i * 2 + 1] = __halves2half2(l2, l3);
}

// W[K,N] fp32 -> Wt [N,K] fp16 (transpose, round-to-nearest). 32x32 tiles.
__global__ __launch_bounds__(256) void convert_T(
    const float* __restrict__ W, __half* __restrict__ hi, int K, int N)
{
    __shared__ float t[32][33];
    const int n0 = blockIdx.x * 32;
    const int k0 = blockIdx.y * 32;
#pragma unroll
    for (int i = 0; i < 4; i++) {
        int k = k0 + threadIdx.y + i * 8;
        t[threadIdx.y + i * 8][threadIdx.x] = W[(size_t)k * N + n0 + threadIdx.x];
    }
    __syncthreads();
#pragma unroll
    for (int i = 0; i < 4; i++) {
        int nn = n0 + threadIdx.y + i * 8;
        hi[(size_t)nn * K + k0 + threadIdx.x] = __float2half(t[threadIdx.x][threadIdx.y + i * 8]);
    }
}

// ---------------------------------------------------------------------------
// fp16 2-MMA split GEMM: C = (Ahi+Alo)[M,K=1024] @ Bh[N,K]^T + bias
// CTA tile 128(M) x 256(N), BK=32, 512 threads (16 warps: 4M x 4N),
// warp tile 32x64. 3-stage cp.async ring, one barrier per kt.
// MODE 0: fp32 C. MODE 1: QKV epilogue -> q split fp16 + k/v fp16 [B,H,T,64].
// ---------------------------------------------------------------------------
#define BK 32
#define ASTRIDE 40                        // fp16 elems per smem row (32 + 8 pad)
#define A_TILE_BYTES (128 * ASTRIDE * 2)  // 10240
#define B_TILE_BYTES (256 * ASTRIDE * 2)  // 20480
#define T_AHI 0
#define T_ALO A_TILE_BYTES
#define T_BH  (2 * A_TILE_BYTES)
#define STAGE_BYTES (2 * A_TILE_BYTES + B_TILE_BYTES)  // 40960
#define GSMEM_TOTAL (3 * STAGE_BYTES)     // 122880

template <int MODE>
__global__ __launch_bounds__(512, 1) void gemm_mma(
    const __half* __restrict__ Ahi, const __half* __restrict__ Alo,
    const __half* __restrict__ Bh,
    const float* __restrict__ bias, float* __restrict__ C,
    __half* __restrict__ qhi, __half* __restrict__ qlo,
    __half* __restrict__ kh, __half* __restrict__ vh,
    int M, int N, int K)
{
    extern __shared__ char smem[];
    const uint32_t smem_base = smem_to_u32(smem);
    const int tid  = threadIdx.x;
    const int wid  = tid >> 5;
    const int lane = tid & 31;
    const int bm = blockIdx.y * 128;
    const int bn = blockIdx.x * 256;
    const int wm = (wid & 3) * 32;
    const int wn = (wid >> 2) * 64;

    auto load_stage = [&](int it) {
        const uint32_t sb = smem_base + (it % 3) * STAGE_BYTES;
        const int k0 = it * BK;
#pragma unroll
        for (int c = tid; c < 2048; c += 512) {
            int kc = (c & 3) * 8;
            const __half* src;
            uint32_t dst;
            if (c < 1024) {            // A hi (c<512) / A lo
                int r = (c & 511) >> 2;
                src = ((c < 512) ? Ahi : Alo) + (size_t)(bm + r) * K + k0 + kc;
                dst = sb + ((c < 512) ? T_AHI : T_ALO) + (r * ASTRIDE + kc) * 2;
            } else {                   // B
                int r = (c - 1024) >> 2;
                src = Bh + (size_t)(bn + r) * K + k0 + kc;
                dst = sb + T_BH + (r * ASTRIDE + kc) * 2;
            }
            cp_async16(dst, src);
        }
    };

    const int NK = K / BK;
    load_stage(0); CP_COMMIT();
    load_stage(1); CP_COMMIT();

    float acc[2][8][4];
#pragma unroll
    for (int mt = 0; mt < 2; mt++)
#pragma unroll
        for (int nt = 0; nt < 8; nt++)
#pragma unroll
            for (int i = 0; i < 4; i++) acc[mt][nt][i] = 0.f;

    const int lrow = lane & 15;
    const int lcol = (lane >> 4) * 8;

    for (int kt = 0; kt < NK; kt++) {
        if (kt + 1 < NK) { CP_WAIT(1); } else { CP_WAIT(0); }
        __syncthreads();       // single barrier per kt (3-stage ring)
        if (kt + 2 < NK) { load_stage(kt + 2); CP_COMMIT(); }
        const uint32_t sb = smem_base + (kt % 3) * STAGE_BYTES;

#pragma unroll
        for (int ks = 0; ks < 2; ks++) {
            uint32_t ah[2][4], al[2][4];
#pragma unroll
            for (int mt = 0; mt < 2; mt++) {
                uint32_t off = ((wm + mt * 16 + lrow) * ASTRIDE + ks * 16 + lcol) * 2;
                ldsm_x4(ah[mt][0], ah[mt][1], ah[mt][2], ah[mt][3], sb + T_AHI + off);
                ldsm_x4(al[mt][0], al[mt][1], al[mt][2], al[mt][3], sb + T_ALO + off);
            }
            uint32_t bh[8][2];
#pragma unroll
            for (int np = 0; np < 4; np++) {
                uint32_t off = ((wn + np * 16 + lrow) * ASTRIDE + ks * 16 + lcol) * 2;
                uint32_t r0, r1, r2, r3;
                ldsm_x4(r0, r1, r2, r3, sb + T_BH + off);
                bh[np * 2][0] = r0; bh[np * 2][1] = r2;
                bh[np * 2 + 1][0] = r1; bh[np * 2 + 1][1] = r3;
            }
#pragma unroll
            for (int mt = 0; mt < 2; mt++)
#pragma unroll
                for (int nt = 0; nt < 8; nt++) {
                    mma_f16(acc[mt][nt], ah[mt], bh[nt]);
                    mma_f16(acc[mt][nt], al[mt], bh[nt]);
                }
        }
    }

    const int trow = lane >> 2;
    const int tcol = (lane & 3) * 2;

    if (MODE == 0) {
#pragma unroll
        for (int mt = 0; mt < 2; mt++) {
            const int grow = bm + wm + mt * 16 + trow;
#pragma unroll
            for (int nt = 0; nt < 8; nt++) {
                const int gcol = bn + wn + nt * 8 + tcol;
                float b0 = bias[gcol], b1 = bias[gcol + 1];
                float2 o0 = {acc[mt][nt][0] + b0, acc[mt][nt][1] + b1};
                float2 o1 = {acc[mt][nt][2] + b0, acc[mt][nt][3] + b1};
                *(float2*)(C + (size_t)grow * N + gcol)       = o0;
                *(float2*)(C + (size_t)(grow + 8) * N + gcol) = o1;
            }
        }
    } else {
        const int sec = bn >> 10;   // 0:q 1:k 2:v (uniform per CTA: 1024%256==0)
        __half* dhi = (sec == 0) ? qhi : (sec == 1) ? kh : vh;
        const float scl = (sec == 0) ? 0.125f : 1.f;
#pragma unroll
        for (int mt = 0; mt < 2; mt++) {
            const int grow = bm + wm + mt * 16 + trow;
#pragma unroll
            for (int nt = 0; nt < 8; nt++) {
                const int gcol = bn + wn + nt * 8 + tcol;
                const int hh = (gcol >> 6) & 15;
                const int dd = gcol & 63;
                float b0 = bias[gcol], b1 = bias[gcol + 1];
#pragma unroll
                for (int rr = 0; rr < 2; rr++) {
                    int row = grow + rr * 8;
                    int t = row >> 1, b_ = row & 1;
                    size_t idx = (((size_t)(b_ * 16 + hh)) * SEQ + t) * 64 + dd;
                    float v0 = (acc[mt][nt][rr * 2]     + b0) * scl;
                    float v1 = (acc[mt][nt][rr * 2 + 1] + b1) * scl;
                    if (sec == 0) {
                        uint32_t hi, lo;
                        split2h(v0, v1, hi, lo);
                        *(uint32_t*)(qhi + idx) = hi;
                        *(uint32_t*)(qlo + idx) = lo;
                    } else {
                        *(uint32_t*)(dhi + idx) = pack2h(v0, v1);
                    }
                }
            }
        }
    }
}

// ---------------------------------------------------------------------------
// Flash attention: q split (2-MMA QK), P in fp16 via ex2.approx.f16x2
// (fragments produced directly), row-sum l via a ones-column MMA on V pad.
// CTA: 128 queries x one (b,h). 8 warps x 16 rows. 64-key tiles, 3-stage
// KV ring, one barrier per k-tile. Output: split fp16 ctx [m][1024].
// ---------------------------------------------------------------------------
#define FQ_HI 0
#define FQ_LO 18432
#define FKV_O 36864
#define FKV_STAGE 18432                // kh 0 | vh 9216
#define FSMEM_TOTAL (FKV_O + 3 * FKV_STAGE + 64)  // +64 slack for ldsm over-read

__global__ __launch_bounds__(256) void flash_mma(
    const __half* __restrict__ qhi, const __half* __restrict__ qlo,
    const __half* __restrict__ kh, const __half* __restrict__ vh,
    __half* __restrict__ chi, __half* __restrict__ clo,
    int nqt)
{
    extern __shared__ char smem[];
    const uint32_t sb = smem_to_u32(smem);
    const int tid  = threadIdx.x;
    const int wid  = tid >> 5;
    const int lane = tid & 31;

    const int bx = blockIdx.x;
    const int bh_ = bx & 31;                // b*16 + h
    const int qt = nqt - 1 - (bx >> 5);     // big tiles first
    const int b_ = bh_ >> 4;
    const int h  = bh_ & 15;
    const int t0 = qt * 128;
    const int nkt = 2 * (qt + 1);
    const size_t hb = ((size_t)(b_ * 16 + h)) * SEQ * 64;

#pragma unroll
    for (int c = tid; c < 2048; c += 256) {
        int tile = c >> 10, r = (c >> 3) & 127, ck = c & 7;
        const __half* src = (tile ? qlo : qhi) + hb + (size_t)(t0 + r) * 64 + ck * 8;
        cp_async16(sb + (tile ? FQ_LO : FQ_HI) + r * 144 + ck * 16, src);
    }
    // ones-column init in V pad (cols 64..71 of each V row, all 3 stages):
    // col64 = 1.0, cols 65..71 = 0.  cp.async never touches these bytes.
    for (int i = tid; i < 3 * 64; i += 256) {
        int stg = i >> 6, r = i & 63;
        uint4 ones = {pack2h(1.f, 0.f), 0u, 0u, 0u};
        *(uint4*)(smem + FKV_O + stg * FKV_STAGE + 9216 + r * 144 + 128) = ones;
    }
    const __half* kvsrc[2] = {kh, vh};
    auto kv_stage = [&](int kt) -> uint32_t {
        return sb + FKV_O + (kt % 3) * FKV_STAGE;
    };
    auto load_kv = [&](int kt) {
        uint32_t st = kv_stage(kt);
        int kt0 = kt * 64;
#pragma unroll
        for (int c = tid; c < 1024; c += 256) {
            int tile = c >> 9, r = (c >> 3) & 63, ck = c & 7;
            cp_async16(st + tile * 9216 + r * 144 + ck * 16,
                       kvsrc[tile] + hb + (size_t)(kt0 + r) * 64 + ck * 8);
        }
    };
    load_kv(0); CP_COMMIT();
    if (nkt > 1) { load_kv(1); CP_COMMIT(); }

    float o[8][4], osum[4];
#pragma unroll
    for (int nt = 0; nt < 8; nt++)
#pragma unroll
        for (int i = 0; i < 4; i++) o[nt][i] = 0.f;
#pragma unroll
    for (int i = 0; i < 4; i++) osum[i] = 0.f;
    float m0 = -1e30f, m1 = -1e30f;

    const int lrow = lane & 15;
    const int lcol = (lane >> 4) * 8;
    const int g    = lane >> 2;
    const int tig  = lane & 3;
    const int wq0  = wid * 16;
    const int row0 = t0 + wq0 + g;
    const int row1 = row0 + 8;
    const float L2E = 1.4426950408889634f;

    for (int kt = 0; kt < nkt; kt++) {
        if (kt + 1 < nkt) { CP_WAIT(1); } else { CP_WAIT(0); }
        __syncthreads();          // single barrier per k-tile
        if (kt + 2 < nkt) { load_kv(kt + 2); CP_COMMIT(); }
        const int kt0 = kt * 64;
        const uint32_t st = kv_stage(kt);

        if (kt0 <= t0 + wq0 + 15) {
            // ---- S = Q @ K^T (2-MMA split: qh + ql, k single) ----
            float s[8][4];
#pragma unroll
            for (int nt = 0; nt < 8; nt++)
#pragma unroll
                for (int i = 0; i < 4; i++) s[nt][i] = 0.f;

#pragma unroll
            for (int ks = 0; ks < 4; ks++) {
                uint32_t ah[4], al[4];
                uint32_t qoff = (wq0 + lrow) * 144 + ks * 32 + lcol * 2;
                ldsm_x4(ah[0], ah[1], ah[2], ah[3], sb + FQ_HI + qoff);
                ldsm_x4(al[0], al[1], al[2], al[3], sb + FQ_LO + qoff);
                uint32_t bkh[8][2];
#pragma unroll
                for (int np = 0; np < 4; np++) {
                    uint32_t koff = (np * 16 + lrow) * 144 + ks * 32 + lcol * 2;
                    uint32_t r0, r1, r2, r3;
                    ldsm_x4(r0, r1, r2, r3, st + koff);
                    bkh[np * 2][0] = r0; bkh[np * 2][1] = r2;
                    bkh[np * 2 + 1][0] = r1; bkh[np * 2 + 1][1] = r3;
                }
#pragma unroll
                for (int nt = 0; nt < 8; nt++) {
                    mma_f16(s[nt], ah, bkh[nt]);
                    mma_f16(s[nt], al, bkh[nt]);
                }
            }

            // ---- causal mask (diagonal band only) ----
            if (kt0 + 63 > t0 + wq0) {
#pragma unroll
                for (int nt = 0; nt < 8; nt++) {
                    int col = kt0 + nt * 8 + tig * 2;
                    if (col     > row0) s[nt][0] = -1e30f;
                    if (col + 1 > row0) s[nt][1] = -1e30f;
                    if (col     > row1) s[nt][2] = -1e30f;
                    if (col + 1 > row1) s[nt][3] = -1e30f;
                }
            }

            // ---- online softmax: max in fp32, exp in fp16x2 ----
            float mx0 = -1e30f, mx1 = -1e30f;
#pragma unroll
            for (int nt = 0; nt < 8; nt++) {
                mx0 = fmaxf(mx0, fmaxf(s[nt][0], s[nt][1]));
                mx1 = fmaxf(mx1, fmaxf(s[nt][2], s[nt][3]));
            }
#pragma unroll
            for (int off = 1; off < 4; off <<= 1) {
                mx0 = fmaxf(mx0, __shfl_xor_sync(0xFFFFFFFFu, mx0, off));
                mx1 = fmaxf(mx1, __shfl_xor_sync(0xFFFFFFFFu, mx1, off));
            }
            float nm0 = fmaxf(m0, mx0), nm1 = fmaxf(m1, mx1);
            float a0 = __expf(m0 - nm0), a1 = __expf(m1 - nm1);
            m0 = nm0; m1 = nm1;
            const float c0 = nm0 * L2E, c1 = nm1 * L2E;

            // P fragments straight from ex2.approx.f16x2
            uint32_t ph[4][4];
#pragma unroll
            for (int ks = 0; ks < 4; ks++) {
                ph[ks][0] = exp2h2(fmaf(s[2*ks][0],   L2E, -c0), fmaf(s[2*ks][1],   L2E, -c0));
                ph[ks][1] = exp2h2(fmaf(s[2*ks][2],   L2E, -c1), fmaf(s[2*ks][3],   L2E, -c1));
                ph[ks][2] = exp2h2(fmaf(s[2*ks+1][0], L2E, -c0), fmaf(s[2*ks+1][1], L2E, -c0));
                ph[ks][3] = exp2h2(fmaf(s[2*ks+1][2], L2E, -c1), fmaf(s[2*ks+1][3], L2E, -c1));
            }

            // rescale accumulators
#pragma unroll
            for (int nt = 0; nt < 8; nt++) {
                o[nt][0] *= a0; o[nt][1] *= a0;
                o[nt][2] *= a1; o[nt][3] *= a1;
            }
            osum[0] *= a0; osum[1] *= a0; osum[2] *= a1; osum[3] *= a1;

            // ---- O += P @ V ;  osum += P @ ones ----
#pragma unroll
            for (int ks = 0; ks < 4; ks++) {
                uint32_t bvh[8][2];
#pragma unroll
                for (int db = 0; db < 4; db++) {
                    uint32_t voff = (ks * 16 + lrow) * 144 + db * 32 + lcol * 2;
                    uint32_t r0, r1, r2, r3;
                    ldsm_x4_t(r0, r1, r2, r3, st + 9216 + voff);
                    bvh[db * 2][0] = r0; bvh[db * 2][1] = r1;
                    bvh[db * 2 + 1][0] = r2; bvh[db * 2 + 1][1] = r3;
                }
#pragma unroll
                for (int nt = 0; nt < 8; nt++) {
                    mma_f16(o[nt], ph[ks], bvh[nt]);
                }
                // ones-column fragment (cols 64..71 of V pad)
                uint32_t bones[2];
                {
                    uint32_t r0, r1, r2, r3;
                    ldsm_x4_t(r0, r1, r2, r3,
                              st + 9216 + (ks * 16 + lrow) * 144 + 128 + lcol * 2);
                    bones[0] = r0; bones[1] = r1;
                }
                mma_f16(osum, ph[ks], bones);
            }
        }
    }

    // ---- epilogue: l from ones-column MMA (col 64 -> tig==0 lanes) ----
    float lz0 = __shfl_sync(0xFFFFFFFFu, osum[0], lane & 28);
    float lz1 = __shfl_sync(0xFFFFFFFFu, osum[2], lane & 28);
    const float i0 = 1.f / lz0;
    const float i1 = 1.f / lz1;
#pragma unroll
    for (int nt = 0; nt < 8; nt++) {
        const int d = nt * 8 + tig * 2;
        size_t o0 = ((size_t)(row0 * BATCH + b_)) * D_MODEL + h * 64 + d;
        size_t o1 = ((size_t)(row1 * BATCH + b_)) * D_MODEL + h * 64 + d;
        uint32_t hi, lo;
        split2h(o[nt][0] * i0, o[nt][1] * i0, hi, lo);
        *(uint32_t*)(chi + o0) = hi;
        *(uint32_t*)(clo + o0) = lo;
        split2h(o[nt][2] * i1, o[nt][3] * i1, hi, lo);
        *(uint32_t*)(chi + o1) = hi;
        *(uint32_t*)(clo + o1) = lo;
    }
}

// ---------------------------------------------------------------------------
extern "C" void kernel_launch(void* const* d_in, const int* in_sizes, int n_in,
                              void* d_out, int out_size)
{
    const float* x    = (const float*)d_in[0];
    const float* Wqkv = (const float*)d_in[1];
    const float* bqkv = (const float*)d_in[2];
    const float* Wout = (const float*)d_in[3];
    const float* bout = (const float*)d_in[4];
    float* out = (float*)d_out;

    const int M = in_sizes[0] / D_MODEL;   // 4096
    const int T = M / BATCH;               // 2048
    const int nqt = T / 128;               // 16

    __half *xhi, *xlo, *w1h, *w2h, *chi, *clo, *qhi, *qlo, *kh, *vh;
    cudaGetSymbolAddress((void**)&xhi, g_xhi);
    cudaGetSymbolAddress((void**)&xlo, g_xlo);
    cudaGetSymbolAddress((void**)&w1h, g_w1h);
    cudaGetSymbolAddress((void**)&w2h, g_w2h);
    cudaGetSymbolAddress((void**)&chi, g_chi);
    cudaGetSymbolAddress((void**)&clo, g_clo);
    cudaGetSymbolAddress((void**)&qhi, g_qhi);
    cudaGetSymbolAddress((void**)&qlo, g_qlo);
    cudaGetSymbolAddress((void**)&kh, g_kh);
    cudaGetSymbolAddress((void**)&vh, g_vh);

    cudaFuncSetAttribute(gemm_mma<0>, cudaFuncAttributeMaxDynamicSharedMemorySize, GSMEM_TOTAL);
    cudaFuncSetAttribute(gemm_mma<1>, cudaFuncAttributeMaxDynamicSharedMemorySize, GSMEM_TOTAL);
    cudaFuncSetAttribute(flash_mma, cudaFuncAttributeMaxDynamicSharedMemorySize, FSMEM_TOTAL);

    // 1) convert inputs
    split_convert<<<(M * D_MODEL / 4 + 255) / 256, 256>>>(x, xhi, xlo, M * D_MODEL / 4);
    convert_T<<<dim3(3 * D_MODEL / 32, D_MODEL / 32), dim3(32, 8)>>>(
        Wqkv, w1h, D_MODEL, 3 * D_MODEL);

    // 2) QKV projection -> q split + k/v fp16 in [B,H,T,64]
    gemm_mma<1><<<dim3(3 * D_MODEL / 256, M / 128), 512, GSMEM_TOTAL>>>(
        xhi, xlo, w1h, bqkv, nullptr,
        qhi, qlo, kh, vh, M, 3 * D_MODEL, D_MODEL);

    // 3) causal flash attention -> split fp16 ctx
    flash_mma<<<32 * nqt, 256, FSMEM_TOTAL>>>(qhi, qlo, kh, vh, chi, clo, nqt);

    // 4) output projection
    convert_T<<<dim3(D_MODEL / 32, D_MODEL / 32), dim3(32, 8)>>>(
        Wout, w2h, D_MODEL, D_MODEL);
    gemm_mma<0><<<dim3(D_MODEL / 256, M / 128), 512, GSMEM_TOTAL>>>(
        chi, clo, w2h, bout, out,
        nullptr, nullptr, nullptr, nullptr, M, D_MODEL, D_MODEL);
}